// round 8
// baseline (speedup 1.0000x reference)
#include <cuda_runtime.h>
#include <cuda_bf16.h>
#include <math.h>
#include <stdint.h>

#define Mq 1024
#define Nn 4096
#define Dd 128
#define Pp 3072
#define Hh 32
#define NKEYS 4096
typedef __nv_bfloat16 bf16;

// ---------------- scratch ----------------
__device__ bf16 g_Xh[(size_t)Mq * Nn],       g_Xl[(size_t)Mq * Nn];
__device__ bf16 g_Qh[(size_t)Hh * Mq * Dd],  g_Ql[(size_t)Hh * Mq * Dd];
__device__ bf16 g_Kh[(size_t)Hh * NKEYS * Dd], g_Kl[(size_t)Hh * NKEYS * Dd];
__device__ bf16 g_Vh[(size_t)Hh * NKEYS * Dd], g_Vl[(size_t)Hh * NKEYS * Dd];

// ---------------- helpers ----------------
static __device__ __forceinline__ uint32_t smem_u32(const void* p) {
    uint32_t a;
    asm("{ .reg .u64 t; cvta.to.shared.u64 t, %1; cvt.u32.u64 %0, t; }" : "=r"(a) : "l"(p));
    return a;
}
static __device__ __forceinline__ void cp_async16(uint32_t dst, const void* src) {
    asm volatile("cp.async.cg.shared.global [%0], [%1], 16;" :: "r"(dst), "l"(src));
}
#define CP_COMMIT() asm volatile("cp.async.commit_group;" ::: "memory")
#define CP_WAIT(n)  asm volatile("cp.async.wait_group %0;" :: "n"(n) : "memory")

static __device__ __forceinline__ void ldsm_x4(uint32_t& r0, uint32_t& r1, uint32_t& r2, uint32_t& r3,
                                               uint32_t addr) {
    asm volatile("ldmatrix.sync.aligned.m8n8.x4.shared.b16 {%0,%1,%2,%3}, [%4];"
                 : "=r"(r0), "=r"(r1), "=r"(r2), "=r"(r3) : "r"(addr));
}
static __device__ __forceinline__ void ldsm_x4_t(uint32_t& r0, uint32_t& r1, uint32_t& r2, uint32_t& r3,
                                                 uint32_t addr) {
    asm volatile("ldmatrix.sync.aligned.m8n8.x4.trans.shared.b16 {%0,%1,%2,%3}, [%4];"
                 : "=r"(r0), "=r"(r1), "=r"(r2), "=r"(r3) : "r"(addr));
}
static __device__ __forceinline__ void mma_bf16(float* c, const uint32_t* a, const uint32_t* b) {
    asm volatile(
        "mma.sync.aligned.m16n8k16.row.col.f32.bf16.bf16.f32 "
        "{%0,%1,%2,%3}, {%4,%5,%6,%7}, {%8,%9}, {%0,%1,%2,%3};"
        : "+f"(c[0]), "+f"(c[1]), "+f"(c[2]), "+f"(c[3])
        : "r"(a[0]), "r"(a[1]), "r"(a[2]), "r"(a[3]), "r"(b[0]), "r"(b[1]));
}
static __device__ __forceinline__ void split_bf16(float v, bf16& h, bf16& l) {
    h = __float2bfloat16(v);
    l = __float2bfloat16(v - __bfloat162float(h));
}
// pack pair to bf16x2 (lo = a, hi = b), plus hi/lo split pair in few ops
static __device__ __forceinline__ uint32_t cvt_bf16x2(float a, float b) {
    uint32_t r;
    asm("cvt.rn.bf16x2.f32 %0, %1, %2;" : "=r"(r) : "f"(b), "f"(a));
    return r;
}
static __device__ __forceinline__ void split_pair(float v0, float v1, uint32_t& ph, uint32_t& pl) {
    ph = cvt_bf16x2(v0, v1);
    const float h0 = __uint_as_float(ph << 16);
    const float h1 = __uint_as_float(ph & 0xFFFF0000u);
    pl = cvt_bf16x2(v0 - h0, v1 - h1);
}

// proj smem: [0,2048) rbuf; 2 stages of (A 64KB + W 32KB) = 96KB
#define PROJ_STAGE 98304
#define SMEM_PROJ (2048 + 2 * PROJ_STAGE)
#define SMEM_ATT  (2048 + 3 * 4 * 16384)

// ---------------- projection GEMM: TM=256, TN=128, W fp32 direct ----------------
// z = 0:Q(RMS), 1:K(RMS,+P), 2:V plain. 512 threads, warp grid 8m x 2n (32x64/warp).
__global__ __launch_bounds__(512, 1) void proj_kernel(
    const bf16* __restrict__ Xh, const bf16* __restrict__ Xl,
    const float* __restrict__ Wq, const float* __restrict__ Wk, const float* __restrict__ Wv)
{
    extern __shared__ char smem[];
    float* rbuf = (float*)smem;
    const uint32_t sb = smem_u32(smem);
    const int tid = threadIdx.x;
    const int wid = tid >> 5, l = tid & 31;
    const int wm = wid >> 1, wn = wid & 1;     // 8m x 2n
    const int bn = blockIdx.x * 128, bm = blockIdx.y * 256, z = blockIdx.z;

    const float* Wp = (z == 0) ? Wq : (z == 1) ? Wk : Wv;

    float acc[2][8][4];
#pragma unroll
    for (int t = 0; t < 2; t++)
#pragma unroll
        for (int nb = 0; nb < 8; nb++)
#pragma unroll
            for (int i = 0; i < 4; i++) acc[t][nb][i] = 0.f;

    const int nch = Nn >> 6;   // 64 chunks of k=64

    // cp.async X planes: [256 rows][128B] per split
    auto load_X = [&](int c) {
        const uint32_t stb = sb + 2048 + (c & 1) * PROJ_STAGE;
        const int k0 = c << 6;
#pragma unroll
        for (int p = 0; p < 2; p++) {
            const bf16* src = p ? Xl : Xh;
#pragma unroll
            for (int i = tid; i < 2048; i += 512) {
                const int row = i >> 3, cc = i & 7;
                const uint32_t off = (uint32_t)(row * 128 + cc * 16);
                cp_async16(stb + p * 32768 + (off ^ (uint32_t)((row & 7) << 4)),
                           src + (size_t)(bm + row) * Nn + k0 + cc * 8);
            }
        }
        CP_COMMIT();
    };

    float4 w4[4];
    auto ldg_W = [&](int c) {
        const int k0 = c << 6;
#pragma unroll
        for (int j = 0; j < 4; j++) {
            const int f = tid + j * 512;       // 0..2047
            const int row = f >> 5, col4 = f & 31;
            w4[j] = __ldg((const float4*)(Wp + (size_t)(k0 + row) * Nn + bn + col4 * 4));
        }
    };
    auto sts_W = [&](int c) {
        char* stc = smem + 2048 + (c & 1) * PROJ_STAGE + 65536;   // W-hi plane; lo at +16384
#pragma unroll
        for (int j = 0; j < 4; j++) {
            const int f = tid + j * 512;
            const int row = f >> 5, col4 = f & 31;
            const uint32_t off = (uint32_t)(row * 256 + col4 * 8);
            const uint32_t sw = off ^ (uint32_t)((row & 7) << 4);
            uint32_t h01, l01, h23, l23;
            split_pair(w4[j].x, w4[j].y, h01, l01);
            split_pair(w4[j].z, w4[j].w, h23, l23);
            *(uint2*)(stc + sw) = make_uint2(h01, h23);
            *(uint2*)(stc + 16384 + sw) = make_uint2(l01, l23);
        }
    };

    ldg_W(0);
    load_X(0);
    load_X(1);

    for (int c = 0; c < nch; c++) {
        if (c + 1 < nch) { CP_WAIT(1); } else { CP_WAIT(0); }
        sts_W(c);
        __syncthreads();
        if (c + 1 < nch) ldg_W(c + 1);

        const uint32_t stb = sb + 2048 + (c & 1) * PROJ_STAGE;
#pragma unroll
        for (int kk = 0; kk < 4; kk++) {
            uint32_t aH[2][4], aL[2][4];
#pragma unroll
            for (int t = 0; t < 2; t++) {
                const int mrow = wm * 32 + t * 16 + (l & 7) + ((l >> 3) & 1) * 8;
                const int kb = kk * 32 + ((l >> 4) & 1) * 16;
                const uint32_t ao = (uint32_t)(mrow * 128) + (uint32_t)(kb ^ ((mrow & 7) << 4));
                ldsm_x4(aH[t][0], aH[t][1], aH[t][2], aH[t][3], stb + ao);
                ldsm_x4(aL[t][0], aL[t][1], aL[t][2], aL[t][3], stb + 32768 + ao);
            }
            uint32_t bH[8][2], bL[8][2];
#pragma unroll
            for (int bt = 0; bt < 4; bt++) {
                const int krow = kk * 16 + (l & 7) + ((l >> 3) & 1) * 8;
                const int colb = wn * 128 + bt * 32 + ((l >> 4) & 1) * 16;
                const uint32_t bo = (uint32_t)(krow * 256) + (uint32_t)(colb ^ ((krow & 7) << 4));
                ldsm_x4_t(bH[2 * bt][0], bH[2 * bt][1], bH[2 * bt + 1][0], bH[2 * bt + 1][1],
                          stb + 65536 + bo);
                ldsm_x4_t(bL[2 * bt][0], bL[2 * bt][1], bL[2 * bt + 1][0], bL[2 * bt + 1][1],
                          stb + 65536 + 16384 + bo);
            }
#pragma unroll
            for (int t = 0; t < 2; t++)
#pragma unroll
                for (int nb = 0; nb < 8; nb++) {
                    mma_bf16(acc[t][nb], aH[t], bH[nb]);
                    mma_bf16(acc[t][nb], aH[t], bL[nb]);
                    mma_bf16(acc[t][nb], aL[t], bH[nb]);
                }
        }
        __syncthreads();
        if (c + 2 < nch) load_X(c + 2);
    }

    // acc[t][nb][i]: row = wm*32+t*16+(l>>2)+(i>>1)*8, col = wn*64+nb*8+(l&3)*2+(i&1)
    if (z < 2) {
        float ss[4] = {0.f, 0.f, 0.f, 0.f};
#pragma unroll
        for (int t = 0; t < 2; t++)
#pragma unroll
            for (int nb = 0; nb < 8; nb++)
#pragma unroll
                for (int i = 0; i < 4; i++) {
                    const float v = acc[t][nb][i];
                    ss[t * 2 + (i >> 1)] += v * v;
                }
#pragma unroll
        for (int s = 0; s < 4; s++) {
            ss[s] += __shfl_xor_sync(0xffffffffu, ss[s], 1);
            ss[s] += __shfl_xor_sync(0xffffffffu, ss[s], 2);
        }
        if ((l & 3) == 0) {
#pragma unroll
            for (int s = 0; s < 4; s++) {
                const int row = wm * 32 + (s >> 1) * 16 + (l >> 2) + (s & 1) * 8;
                rbuf[wn * 256 + row] = ss[s];
            }
        }
        __syncthreads();
    }

    bf16* dh = (z == 0) ? g_Qh : (z == 1) ? g_Kh : g_Vh;
    bf16* dl = (z == 0) ? g_Ql : (z == 1) ? g_Kl : g_Vl;
#pragma unroll
    for (int t = 0; t < 2; t++)
#pragma unroll
        for (int rh = 0; rh < 2; rh++) {
            const int row = wm * 32 + t * 16 + (l >> 2) + rh * 8;
            float sc = 1.0f;
            if (z < 2) sc = rsqrtf((rbuf[row] + rbuf[256 + row]) * (1.0f / 128.0f));
            const size_t rowbase = (z == 0)
                ? ((size_t)blockIdx.x * Mq + bm + row) * 128
                : ((size_t)blockIdx.x * NKEYS + Pp + bm + row) * 128;
#pragma unroll
            for (int nb = 0; nb < 8; nb++) {
                const int col = wn * 64 + nb * 8 + (l & 3) * 2;
                uint32_t ph, pl;
                split_pair(acc[t][nb][rh * 2 + 0] * sc, acc[t][nb][rh * 2 + 1] * sc, ph, pl);
                *(uint32_t*)(dh + rowbase + col) = ph;
                *(uint32_t*)(dl + rowbase + col) = pl;
            }
        }
}

// ---------------- fused flash attention, 512 threads ----------------
__global__ __launch_bounds__(512, 1) void attn_kernel(float* __restrict__ outp)
{
    extern __shared__ char smem[];
    float* rbuf = (float*)smem;
    const uint32_t sb = smem_u32(smem);
    const uint32_t Qb = sb + 2048;
    const uint32_t Kb = Qb + 65536;
    const uint32_t Vb = Kb + 65536;
    char* Kc = smem + 2048 + 65536;

    const int tid = threadIdx.x;
    const int wid = tid >> 5, l = tid & 31;
    const int wm = wid >> 2, wn = wid & 3;
    const int bm = blockIdx.x * 128;
    const int z = blockIdx.y;

    const bf16* Qhp = g_Qh + ((size_t)z * Mq + bm) * Dd;
    const bf16* Qlp = g_Ql + ((size_t)z * Mq + bm) * Dd;
    const bf16* Khp = g_Kh + (size_t)z * NKEYS * Dd;
    const bf16* Klp = g_Kl + (size_t)z * NKEYS * Dd;
    const bf16* Vhp = g_Vh + (size_t)z * NKEYS * Dd;
    const bf16* Vlp = g_Vl + (size_t)z * NKEYS * Dd;

    auto load_region = [&](uint32_t dstb, const bf16* srcH, const bf16* srcL, int row0) {
#pragma unroll
        for (int p = 0; p < 4; p++) {
            const bf16* src = (p < 2) ? srcH : srcL;
            const int k0 = (p & 1) * 64;
#pragma unroll
            for (int i = tid; i < 1024; i += 512) {
                const int row = i >> 3, cc = i & 7;
                const uint32_t off = (uint32_t)(row * 128 + cc * 16);
                cp_async16(dstb + p * 16384 + (off ^ (uint32_t)((row & 7) << 4)),
                           src + (size_t)(row0 + row) * Dd + k0 + cc * 8);
            }
        }
    };
    auto load_v = [&](int bn) {
#pragma unroll
        for (int p = 0; p < 2; p++) {
            const bf16* src = p ? Vlp : Vhp;
#pragma unroll
            for (int i = tid; i < 2048; i += 512) {
                const int row = i >> 4, c16 = i & 15;
                const uint32_t off = (uint32_t)(row * 256 + c16 * 16);
                cp_async16(Vb + p * 32768 + (off ^ (uint32_t)((row & 7) << 4)),
                           src + (size_t)(bn + row) * Dd + c16 * 8);
            }
        }
    };

    auto do_mma_qk = [&](float acc[2][4][4]) {
#pragma unroll
        for (int c = 0; c < 2; c++) {
            const uint32_t aHb = Qb + c * 16384, aLb = Qb + (2 + c) * 16384;
            const uint32_t bHb = Kb + c * 16384, bLb = Kb + (2 + c) * 16384;
#pragma unroll
            for (int kk = 0; kk < 4; kk++) {
                uint32_t aH[2][4], aL[2][4];
#pragma unroll
                for (int t = 0; t < 2; t++) {
                    const int mrow = wm * 32 + t * 16 + (l & 7) + ((l >> 3) & 1) * 8;
                    const int kb = kk * 32 + ((l >> 4) & 1) * 16;
                    const uint32_t ao = (uint32_t)(mrow * 128) + (uint32_t)(kb ^ ((mrow & 7) << 4));
                    ldsm_x4(aH[t][0], aH[t][1], aH[t][2], aH[t][3], aHb + ao);
                    ldsm_x4(aL[t][0], aL[t][1], aL[t][2], aL[t][3], aLb + ao);
                }
                uint32_t bH[4][2], bL[4][2];
#pragma unroll
                for (int bt = 0; bt < 2; bt++) {
                    const int nrow = wn * 32 + bt * 16 + (l & 7) + ((l >> 4) & 1) * 8;
                    const int kb = kk * 32 + ((l >> 3) & 1) * 16;
                    const uint32_t bo = (uint32_t)(nrow * 128) + (uint32_t)(kb ^ ((nrow & 7) << 4));
                    ldsm_x4(bH[2 * bt][0], bH[2 * bt][1], bH[2 * bt + 1][0], bH[2 * bt + 1][1], bHb + bo);
                    ldsm_x4(bL[2 * bt][0], bL[2 * bt][1], bL[2 * bt + 1][0], bL[2 * bt + 1][1], bLb + bo);
                }
#pragma unroll
                for (int t = 0; t < 2; t++)
#pragma unroll
                    for (int nb = 0; nb < 4; nb++) {
                        mma_bf16(acc[t][nb], aH[t], bH[nb]);
                        mma_bf16(acc[t][nb], aH[t], bL[nb]);
                        mma_bf16(acc[t][nb], aL[t], bH[nb]);
                    }
            }
        }
    };

    auto do_mma_pv = [&](float acc[2][4][4]) {
#pragma unroll
        for (int c = 0; c < 2; c++) {
            const uint32_t aHb = Kb + c * 16384, aLb = Kb + (2 + c) * 16384;
#pragma unroll
            for (int kk = 0; kk < 4; kk++) {
                uint32_t aH[2][4], aL[2][4];
#pragma unroll
                for (int t = 0; t < 2; t++) {
                    const int mrow = wm * 32 + t * 16 + (l & 7) + ((l >> 3) & 1) * 8;
                    const int kb = kk * 32 + ((l >> 4) & 1) * 16;
                    const uint32_t ao = (uint32_t)(mrow * 128) + (uint32_t)(kb ^ ((mrow & 7) << 4));
                    ldsm_x4(aH[t][0], aH[t][1], aH[t][2], aH[t][3], aHb + ao);
                    ldsm_x4(aL[t][0], aL[t][1], aL[t][2], aL[t][3], aLb + ao);
                }
                uint32_t bH[4][2], bL[4][2];
#pragma unroll
                for (int bt = 0; bt < 2; bt++) {
                    const int key = c * 64 + kk * 16 + (l & 7) + ((l >> 3) & 1) * 8;
                    const int colb = wn * 64 + bt * 32 + ((l >> 4) & 1) * 16;
                    const uint32_t bo = (uint32_t)(key * 256) + (uint32_t)(colb ^ ((key & 7) << 4));
                    ldsm_x4_t(bH[2 * bt][0], bH[2 * bt][1], bH[2 * bt + 1][0], bH[2 * bt + 1][1],
                              Vb + 0 * 32768 + bo);
                    ldsm_x4_t(bL[2 * bt][0], bL[2 * bt][1], bL[2 * bt + 1][0], bL[2 * bt + 1][1],
                              Vb + 1 * 32768 + bo);
                }
#pragma unroll
                for (int t = 0; t < 2; t++)
#pragma unroll
                    for (int nb = 0; nb < 4; nb++) {
                        mma_bf16(acc[t][nb], aH[t], bH[nb]);
                        mma_bf16(acc[t][nb], aH[t], bL[nb]);
                        mma_bf16(acc[t][nb], aL[t], bH[nb]);
                    }
            }
        }
    };

    float accO[2][4][4];
#pragma unroll
    for (int t = 0; t < 2; t++)
#pragma unroll
        for (int nb = 0; nb < 4; nb++)
#pragma unroll
            for (int i = 0; i < 4; i++) accO[t][nb][i] = 0.f;
    float rs[4] = {0.f, 0.f, 0.f, 0.f};

    load_region(Qb, Qhp, Qlp, 0);
    load_region(Kb, Khp, Klp, 0);
    CP_COMMIT();

    for (int it = 0; it < NKEYS / 128; it++) {
        const int bn = it * 128;
        load_v(bn);
        CP_COMMIT();

        CP_WAIT(1);
        __syncthreads();

        float accS[2][4][4];
#pragma unroll
        for (int t = 0; t < 2; t++)
#pragma unroll
            for (int nb = 0; nb < 4; nb++)
#pragma unroll
                for (int i = 0; i < 4; i++) accS[t][nb][i] = 0.f;

        do_mma_qk(accS);
        __syncthreads();

#pragma unroll
        for (int t = 0; t < 2; t++)
#pragma unroll
            for (int rh = 0; rh < 2; rh++) {
                const int row = wm * 32 + t * 16 + (l >> 2) + rh * 8;
#pragma unroll
                for (int nb = 0; nb < 4; nb++) {
                    const int col = wn * 32 + nb * 8 + (l & 3) * 2;
                    const float e0 = __expf(accS[t][nb][rh * 2 + 0]);
                    const float e1 = __expf(accS[t][nb][rh * 2 + 1]);
                    rs[t * 2 + rh] += e0 + e1;
                    uint32_t ph, pl;
                    split_pair(e0, e1, ph, pl);
                    const uint32_t off = (uint32_t)(row * 128 + (col & 63) * 2);
                    const uint32_t sw = off ^ (uint32_t)((row & 7) << 4);
                    const int chunk = wn >> 1;
                    *(uint32_t*)(Kc + (0 * 2 + chunk) * 16384 + sw) = ph;
                    *(uint32_t*)(Kc + (1 * 2 + chunk) * 16384 + sw) = pl;
                }
            }
        CP_WAIT(0);
        __syncthreads();

        do_mma_pv(accO);
        __syncthreads();

        if (it + 1 < NKEYS / 128) {
            load_region(Kb, Khp, Klp, bn + 128);
            CP_COMMIT();
        }
    }

#pragma unroll
    for (int s = 0; s < 4; s++) {
        rs[s] += __shfl_xor_sync(0xffffffffu, rs[s], 1);
        rs[s] += __shfl_xor_sync(0xffffffffu, rs[s], 2);
    }
    if ((l & 3) == 0) {
#pragma unroll
        for (int s = 0; s < 4; s++) {
            const int row = wm * 32 + (s >> 1) * 16 + (l >> 2) + (s & 1) * 8;
            rbuf[wn * 128 + row] = rs[s];
        }
    }
    __syncthreads();

#pragma unroll
    for (int t = 0; t < 2; t++)
#pragma unroll
        for (int rh = 0; rh < 2; rh++) {
            const int row = wm * 32 + t * 16 + (l >> 2) + rh * 8;
            const float inv = 1.0f / (rbuf[row] + rbuf[128 + row] + rbuf[256 + row] + rbuf[384 + row]);
            float* orow = outp + (size_t)(bm + row) * Nn + (size_t)z * Dd;
#pragma unroll
            for (int nb = 0; nb < 4; nb++) {
                const int col = wn * 32 + nb * 8 + (l & 3) * 2;
                float2 v;
                v.x = accO[t][nb][rh * 2 + 0] * inv;
                v.y = accO[t][nb][rh * 2 + 1] * inv;
                *(float2*)(orow + col) = v;
            }
        }
}

// ---------------- prep ----------------
__global__ __launch_bounds__(256) void convert_inputs(
    const float* __restrict__ X, const float* __restrict__ cK, const float* __restrict__ cV)
{
    const size_t stride = (size_t)gridDim.x * blockDim.x;
    const size_t tid0 = (size_t)blockIdx.x * blockDim.x + threadIdx.x;

    for (size_t i = tid0; i < (size_t)Mq * Nn; i += stride) {
        bf16 h, lo;
        split_bf16(X[i], h, lo);
        g_Xh[i] = h; g_Xl[i] = lo;
    }
    const size_t nkv = (size_t)Hh * Pp * Dd;
    for (size_t i = tid0; i < nkv; i += stride) {
        const size_t h = i / ((size_t)Pp * Dd);
        const size_t r = i % ((size_t)Pp * Dd);
        const size_t o = h * (size_t)NKEYS * Dd + r;
        bf16 hh, lo;
        split_bf16(cK[i], hh, lo);
        g_Kh[o] = hh; g_Kl[o] = lo;
        split_bf16(cV[i], hh, lo);
        g_Vh[o] = hh; g_Vl[o] = lo;
    }
}

// ---------------- host launcher ----------------
extern "C" void kernel_launch(void* const* d_in, const int* in_sizes, int n_in,
                              void* d_out, int out_size)
{
    const float* X  = (const float*)d_in[0];
    const float* Wq = (const float*)d_in[1];
    const float* Wk = (const float*)d_in[2];
    const float* Wv = (const float*)d_in[3];
    const float* cK = (const float*)d_in[4];
    const float* cV = (const float*)d_in[5];
    float* out = (float*)d_out;

    bf16 *xh, *xl;
    cudaGetSymbolAddress((void**)&xh, g_Xh);
    cudaGetSymbolAddress((void**)&xl, g_Xl);

    cudaFuncSetAttribute(proj_kernel, cudaFuncAttributeMaxDynamicSharedMemorySize, SMEM_PROJ);
    cudaFuncSetAttribute(attn_kernel, cudaFuncAttributeMaxDynamicSharedMemorySize, SMEM_ATT);

    convert_inputs<<<4096, 256>>>(X, cK, cV);

    proj_kernel<<<dim3(Nn / 128, Mq / 256, 3), 512, SMEM_PROJ>>>(xh, xl, Wq, Wk, Wv);

    attn_kernel<<<dim3(Mq / 128, Hh), 512, SMEM_ATT>>>(out);
}

// round 9
// speedup vs baseline: 1.1040x; 1.1040x over previous
#include <cuda_runtime.h>
#include <cuda_bf16.h>
#include <math.h>
#include <stdint.h>

#define Mq 1024
#define Nn 4096
#define Dd 128
#define Pp 3072
#define Hh 32
#define NKEYS 4096
typedef __nv_bfloat16 bf16;

// ---------------- scratch ----------------
__device__ bf16 g_Xh[(size_t)Mq * Nn],       g_Xl[(size_t)Mq * Nn];
__device__ bf16 g_Wh[(size_t)3 * Nn * Nn],   g_Wl[(size_t)3 * Nn * Nn];      // natural [k][n]
__device__ bf16 g_Qh[(size_t)Hh * Mq * Dd],  g_Ql[(size_t)Hh * Mq * Dd];
__device__ bf16 g_Kh[(size_t)Hh * NKEYS * Dd], g_Kl[(size_t)Hh * NKEYS * Dd];
__device__ bf16 g_Vh[(size_t)Hh * NKEYS * Dd], g_Vl[(size_t)Hh * NKEYS * Dd];

// ---------------- helpers ----------------
static __device__ __forceinline__ uint32_t smem_u32(const void* p) {
    uint32_t a;
    asm("{ .reg .u64 t; cvta.to.shared.u64 t, %1; cvt.u32.u64 %0, t; }" : "=r"(a) : "l"(p));
    return a;
}
static __device__ __forceinline__ void cp_async16(uint32_t dst, const void* src) {
    asm volatile("cp.async.cg.shared.global [%0], [%1], 16;" :: "r"(dst), "l"(src));
}
#define CP_COMMIT() asm volatile("cp.async.commit_group;" ::: "memory")
#define CP_WAIT(n)  asm volatile("cp.async.wait_group %0;" :: "n"(n) : "memory")

static __device__ __forceinline__ void ldsm_x4(uint32_t& r0, uint32_t& r1, uint32_t& r2, uint32_t& r3,
                                               uint32_t addr) {
    asm volatile("ldmatrix.sync.aligned.m8n8.x4.shared.b16 {%0,%1,%2,%3}, [%4];"
                 : "=r"(r0), "=r"(r1), "=r"(r2), "=r"(r3) : "r"(addr));
}
static __device__ __forceinline__ void ldsm_x4_t(uint32_t& r0, uint32_t& r1, uint32_t& r2, uint32_t& r3,
                                                 uint32_t addr) {
    asm volatile("ldmatrix.sync.aligned.m8n8.x4.trans.shared.b16 {%0,%1,%2,%3}, [%4];"
                 : "=r"(r0), "=r"(r1), "=r"(r2), "=r"(r3) : "r"(addr));
}
static __device__ __forceinline__ void mma_bf16(float* c, const uint32_t* a, const uint32_t* b) {
    asm volatile(
        "mma.sync.aligned.m16n8k16.row.col.f32.bf16.bf16.f32 "
        "{%0,%1,%2,%3}, {%4,%5,%6,%7}, {%8,%9}, {%0,%1,%2,%3};"
        : "+f"(c[0]), "+f"(c[1]), "+f"(c[2]), "+f"(c[3])
        : "r"(a[0]), "r"(a[1]), "r"(a[2]), "r"(a[3]), "r"(b[0]), "r"(b[1]));
}
static __device__ __forceinline__ void split_bf16(float v, bf16& h, bf16& l) {
    h = __float2bfloat16(v);
    l = __float2bfloat16(v - __bfloat162float(h));
}
static __device__ __forceinline__ uint32_t cvt_bf16x2(float a, float b) {
    uint32_t r;
    asm("cvt.rn.bf16x2.f32 %0, %1, %2;" : "=r"(r) : "f"(b), "f"(a));
    return r;
}
static __device__ __forceinline__ void split_pair(float v0, float v1, uint32_t& ph, uint32_t& pl) {
    ph = cvt_bf16x2(v0, v1);
    const float h0 = __uint_as_float(ph << 16);
    const float h1 = __uint_as_float(ph & 0xFFFF0000u);
    pl = cvt_bf16x2(v0 - h0, v1 - h1);
}

// proj smem: rbuf 2048; 2 stages of (A 64KB + W 32KB)
#define PROJ_STAGE 98304
#define SMEM_PROJ (2048 + 2 * PROJ_STAGE)
#define SMEM_ATT  (2048 + 3 * 4 * 16384)

// ---------------- projection GEMM: TM=256, TN=128, 256 threads ----------------
// z = 0:Q(RMS), 1:K(RMS,+P), 2:V plain. Warp grid 4m x 2n, warp tile 64x64.
__global__ __launch_bounds__(256, 1) void proj_kernel(
    const bf16* __restrict__ Xh, const bf16* __restrict__ Xl,
    const bf16* __restrict__ Wh, const bf16* __restrict__ Wl)
{
    extern __shared__ char smem[];
    float* rbuf = (float*)smem;
    const uint32_t sb = smem_u32(smem);
    const int tid = threadIdx.x;
    const int wid = tid >> 5, l = tid & 31;
    const int wm = wid >> 1, wn = wid & 1;     // 4m x 2n
    const int bn = blockIdx.x * 128, bm = blockIdx.y * 256, z = blockIdx.z;

    const bf16* WhP = Wh + (size_t)z * Nn * Nn;
    const bf16* WlP = Wl + (size_t)z * Nn * Nn;

    float acc[4][8][4];
#pragma unroll
    for (int t = 0; t < 4; t++)
#pragma unroll
        for (int nb = 0; nb < 8; nb++)
#pragma unroll
            for (int i = 0; i < 4; i++) acc[t][nb][i] = 0.f;

    const int nch = Nn >> 6;   // 64 chunks of k=64

    auto load_chunk = [&](int c) {
        const uint32_t stb = sb + 2048 + (c & 1) * PROJ_STAGE;
        const int k0 = c << 6;
        // A planes: [256 rows][128B] per split (32KB each)
#pragma unroll
        for (int p = 0; p < 2; p++) {
            const bf16* src = p ? Xl : Xh;
#pragma unroll
            for (int i = tid; i < 2048; i += 256) {
                const int row = i >> 3, cc = i & 7;
                const uint32_t off = (uint32_t)(row * 128 + cc * 16);
                cp_async16(stb + p * 32768 + (off ^ (uint32_t)((row & 7) << 4)),
                           src + (size_t)(bm + row) * Nn + k0 + cc * 8);
            }
        }
        // B planes: [64 k][256B] per split (16KB each), natural W rows
#pragma unroll
        for (int p = 0; p < 2; p++) {
            const bf16* src = p ? WlP : WhP;
#pragma unroll
            for (int i = tid; i < 1024; i += 256) {
                const int row = i >> 4, c16 = i & 15;
                const uint32_t off = (uint32_t)(row * 256 + c16 * 16);
                cp_async16(stb + 65536 + p * 16384 + (off ^ (uint32_t)((row & 7) << 4)),
                           src + (size_t)(k0 + row) * Nn + bn + c16 * 8);
            }
        }
        CP_COMMIT();
    };

    load_chunk(0);
    load_chunk(1);

    for (int c = 0; c < nch; c++) {
        if (c + 1 < nch) { CP_WAIT(1); } else { CP_WAIT(0); }
        __syncthreads();
        const uint32_t stb = sb + 2048 + (c & 1) * PROJ_STAGE;

#pragma unroll
        for (int kk = 0; kk < 4; kk++) {
            uint32_t bH[8][2], bL[8][2];
#pragma unroll
            for (int bt = 0; bt < 4; bt++) {
                const int krow = kk * 16 + (l & 7) + ((l >> 3) & 1) * 8;
                const int colb = wn * 128 + bt * 32 + ((l >> 4) & 1) * 16;   // bytes
                const uint32_t bo = (uint32_t)(krow * 256) + (uint32_t)(colb ^ ((krow & 7) << 4));
                ldsm_x4_t(bH[2 * bt][0], bH[2 * bt][1], bH[2 * bt + 1][0], bH[2 * bt + 1][1],
                          stb + 65536 + bo);
                ldsm_x4_t(bL[2 * bt][0], bL[2 * bt][1], bL[2 * bt + 1][0], bL[2 * bt + 1][1],
                          stb + 65536 + 16384 + bo);
            }
#pragma unroll
            for (int t = 0; t < 4; t++) {
                uint32_t aH[4], aL[4];
                const int mrow = wm * 64 + t * 16 + (l & 7) + ((l >> 3) & 1) * 8;
                const int kb = kk * 32 + ((l >> 4) & 1) * 16;
                const uint32_t ao = (uint32_t)(mrow * 128) + (uint32_t)(kb ^ ((mrow & 7) << 4));
                ldsm_x4(aH[0], aH[1], aH[2], aH[3], stb + ao);
                ldsm_x4(aL[0], aL[1], aL[2], aL[3], stb + 32768 + ao);
#pragma unroll
                for (int nb = 0; nb < 8; nb++) {
                    mma_bf16(acc[t][nb], aH, bH[nb]);
                    mma_bf16(acc[t][nb], aH, bL[nb]);
                    mma_bf16(acc[t][nb], aL, bH[nb]);
                }
            }
        }
        __syncthreads();
        if (c + 2 < nch) load_chunk(c + 2);
    }

    // acc[t][nb][i]: row = wm*64 + t*16 + (l>>2) + (i>>1)*8, col = wn*64 + nb*8 + (l&3)*2 + (i&1)
    if (z < 2) {
        float ss[8];
#pragma unroll
        for (int s = 0; s < 8; s++) ss[s] = 0.f;
#pragma unroll
        for (int t = 0; t < 4; t++)
#pragma unroll
            for (int nb = 0; nb < 8; nb++)
#pragma unroll
                for (int i = 0; i < 4; i++) {
                    const float v = acc[t][nb][i];
                    ss[t * 2 + (i >> 1)] += v * v;
                }
#pragma unroll
        for (int s = 0; s < 8; s++) {
            ss[s] += __shfl_xor_sync(0xffffffffu, ss[s], 1);
            ss[s] += __shfl_xor_sync(0xffffffffu, ss[s], 2);
        }
        if ((l & 3) == 0) {
#pragma unroll
            for (int s = 0; s < 8; s++) {
                const int row = wm * 64 + (s >> 1) * 16 + (l >> 2) + (s & 1) * 8;
                rbuf[wn * 256 + row] = ss[s];
            }
        }
        __syncthreads();
    }

    bf16* dh = (z == 0) ? g_Qh : (z == 1) ? g_Kh : g_Vh;
    bf16* dl = (z == 0) ? g_Ql : (z == 1) ? g_Kl : g_Vl;
#pragma unroll
    for (int t = 0; t < 4; t++)
#pragma unroll
        for (int rh = 0; rh < 2; rh++) {
            const int row = wm * 64 + t * 16 + (l >> 2) + rh * 8;
            float sc = 1.0f;
            if (z < 2) sc = rsqrtf((rbuf[row] + rbuf[256 + row]) * (1.0f / 128.0f));
            const size_t rowbase = (z == 0)
                ? ((size_t)blockIdx.x * Mq + bm + row) * 128
                : ((size_t)blockIdx.x * NKEYS + Pp + bm + row) * 128;
#pragma unroll
            for (int nb = 0; nb < 8; nb++) {
                const int col = wn * 64 + nb * 8 + (l & 3) * 2;
                uint32_t ph, pl;
                split_pair(acc[t][nb][rh * 2 + 0] * sc, acc[t][nb][rh * 2 + 1] * sc, ph, pl);
                *(uint32_t*)(dh + rowbase + col) = ph;
                *(uint32_t*)(dl + rowbase + col) = pl;
            }
        }
}

// ---------------- fused flash attention, 512 threads (unchanged from R7/R8) ----------------
__global__ __launch_bounds__(512, 1) void attn_kernel(float* __restrict__ outp)
{
    extern __shared__ char smem[];
    float* rbuf = (float*)smem;
    const uint32_t sb = smem_u32(smem);
    const uint32_t Qb = sb + 2048;
    const uint32_t Kb = Qb + 65536;
    const uint32_t Vb = Kb + 65536;
    char* Kc = smem + 2048 + 65536;

    const int tid = threadIdx.x;
    const int wid = tid >> 5, l = tid & 31;
    const int wm = wid >> 2, wn = wid & 3;
    const int bm = blockIdx.x * 128;
    const int z = blockIdx.y;

    const bf16* Qhp = g_Qh + ((size_t)z * Mq + bm) * Dd;
    const bf16* Qlp = g_Ql + ((size_t)z * Mq + bm) * Dd;
    const bf16* Khp = g_Kh + (size_t)z * NKEYS * Dd;
    const bf16* Klp = g_Kl + (size_t)z * NKEYS * Dd;
    const bf16* Vhp = g_Vh + (size_t)z * NKEYS * Dd;
    const bf16* Vlp = g_Vl + (size_t)z * NKEYS * Dd;

    auto load_region = [&](uint32_t dstb, const bf16* srcH, const bf16* srcL, int row0) {
#pragma unroll
        for (int p = 0; p < 4; p++) {
            const bf16* src = (p < 2) ? srcH : srcL;
            const int k0 = (p & 1) * 64;
#pragma unroll
            for (int i = tid; i < 1024; i += 512) {
                const int row = i >> 3, cc = i & 7;
                const uint32_t off = (uint32_t)(row * 128 + cc * 16);
                cp_async16(dstb + p * 16384 + (off ^ (uint32_t)((row & 7) << 4)),
                           src + (size_t)(row0 + row) * Dd + k0 + cc * 8);
            }
        }
    };
    auto load_v = [&](int bn) {
#pragma unroll
        for (int p = 0; p < 2; p++) {
            const bf16* src = p ? Vlp : Vhp;
#pragma unroll
            for (int i = tid; i < 2048; i += 512) {
                const int row = i >> 4, c16 = i & 15;
                const uint32_t off = (uint32_t)(row * 256 + c16 * 16);
                cp_async16(Vb + p * 32768 + (off ^ (uint32_t)((row & 7) << 4)),
                           src + (size_t)(bn + row) * Dd + c16 * 8);
            }
        }
    };

    auto do_mma_qk = [&](float acc[2][4][4]) {
#pragma unroll
        for (int c = 0; c < 2; c++) {
            const uint32_t aHb = Qb + c * 16384, aLb = Qb + (2 + c) * 16384;
            const uint32_t bHb = Kb + c * 16384, bLb = Kb + (2 + c) * 16384;
#pragma unroll
            for (int kk = 0; kk < 4; kk++) {
                uint32_t aH[2][4], aL[2][4];
#pragma unroll
                for (int t = 0; t < 2; t++) {
                    const int mrow = wm * 32 + t * 16 + (l & 7) + ((l >> 3) & 1) * 8;
                    const int kb = kk * 32 + ((l >> 4) & 1) * 16;
                    const uint32_t ao = (uint32_t)(mrow * 128) + (uint32_t)(kb ^ ((mrow & 7) << 4));
                    ldsm_x4(aH[t][0], aH[t][1], aH[t][2], aH[t][3], aHb + ao);
                    ldsm_x4(aL[t][0], aL[t][1], aL[t][2], aL[t][3], aLb + ao);
                }
                uint32_t bH[4][2], bL[4][2];
#pragma unroll
                for (int bt = 0; bt < 2; bt++) {
                    const int nrow = wn * 32 + bt * 16 + (l & 7) + ((l >> 4) & 1) * 8;
                    const int kb = kk * 32 + ((l >> 3) & 1) * 16;
                    const uint32_t bo = (uint32_t)(nrow * 128) + (uint32_t)(kb ^ ((nrow & 7) << 4));
                    ldsm_x4(bH[2 * bt][0], bH[2 * bt][1], bH[2 * bt + 1][0], bH[2 * bt + 1][1], bHb + bo);
                    ldsm_x4(bL[2 * bt][0], bL[2 * bt][1], bL[2 * bt + 1][0], bL[2 * bt + 1][1], bLb + bo);
                }
#pragma unroll
                for (int t = 0; t < 2; t++)
#pragma unroll
                    for (int nb = 0; nb < 4; nb++) {
                        mma_bf16(acc[t][nb], aH[t], bH[nb]);
                        mma_bf16(acc[t][nb], aH[t], bL[nb]);
                        mma_bf16(acc[t][nb], aL[t], bH[nb]);
                    }
            }
        }
    };

    auto do_mma_pv = [&](float acc[2][4][4]) {
#pragma unroll
        for (int c = 0; c < 2; c++) {
            const uint32_t aHb = Kb + c * 16384, aLb = Kb + (2 + c) * 16384;
#pragma unroll
            for (int kk = 0; kk < 4; kk++) {
                uint32_t aH[2][4], aL[2][4];
#pragma unroll
                for (int t = 0; t < 2; t++) {
                    const int mrow = wm * 32 + t * 16 + (l & 7) + ((l >> 3) & 1) * 8;
                    const int kb = kk * 32 + ((l >> 4) & 1) * 16;
                    const uint32_t ao = (uint32_t)(mrow * 128) + (uint32_t)(kb ^ ((mrow & 7) << 4));
                    ldsm_x4(aH[t][0], aH[t][1], aH[t][2], aH[t][3], aHb + ao);
                    ldsm_x4(aL[t][0], aL[t][1], aL[t][2], aL[t][3], aLb + ao);
                }
                uint32_t bH[4][2], bL[4][2];
#pragma unroll
                for (int bt = 0; bt < 2; bt++) {
                    const int key = c * 64 + kk * 16 + (l & 7) + ((l >> 3) & 1) * 8;
                    const int colb = wn * 64 + bt * 32 + ((l >> 4) & 1) * 16;
                    const uint32_t bo = (uint32_t)(key * 256) + (uint32_t)(colb ^ ((key & 7) << 4));
                    ldsm_x4_t(bH[2 * bt][0], bH[2 * bt][1], bH[2 * bt + 1][0], bH[2 * bt + 1][1],
                              Vb + 0 * 32768 + bo);
                    ldsm_x4_t(bL[2 * bt][0], bL[2 * bt][1], bL[2 * bt + 1][0], bL[2 * bt + 1][1],
                              Vb + 1 * 32768 + bo);
                }
#pragma unroll
                for (int t = 0; t < 2; t++)
#pragma unroll
                    for (int nb = 0; nb < 4; nb++) {
                        mma_bf16(acc[t][nb], aH[t], bH[nb]);
                        mma_bf16(acc[t][nb], aH[t], bL[nb]);
                        mma_bf16(acc[t][nb], aL[t], bH[nb]);
                    }
            }
        }
    };

    float accO[2][4][4];
#pragma unroll
    for (int t = 0; t < 2; t++)
#pragma unroll
        for (int nb = 0; nb < 4; nb++)
#pragma unroll
            for (int i = 0; i < 4; i++) accO[t][nb][i] = 0.f;
    float rs[4] = {0.f, 0.f, 0.f, 0.f};

    load_region(Qb, Qhp, Qlp, 0);
    load_region(Kb, Khp, Klp, 0);
    CP_COMMIT();

    for (int it = 0; it < NKEYS / 128; it++) {
        const int bn = it * 128;
        load_v(bn);
        CP_COMMIT();

        CP_WAIT(1);
        __syncthreads();

        float accS[2][4][4];
#pragma unroll
        for (int t = 0; t < 2; t++)
#pragma unroll
            for (int nb = 0; nb < 4; nb++)
#pragma unroll
                for (int i = 0; i < 4; i++) accS[t][nb][i] = 0.f;

        do_mma_qk(accS);
        __syncthreads();

#pragma unroll
        for (int t = 0; t < 2; t++)
#pragma unroll
            for (int rh = 0; rh < 2; rh++) {
                const int row = wm * 32 + t * 16 + (l >> 2) + rh * 8;
#pragma unroll
                for (int nb = 0; nb < 4; nb++) {
                    const int col = wn * 32 + nb * 8 + (l & 3) * 2;
                    const float e0 = __expf(accS[t][nb][rh * 2 + 0]);
                    const float e1 = __expf(accS[t][nb][rh * 2 + 1]);
                    rs[t * 2 + rh] += e0 + e1;
                    uint32_t ph, pl;
                    split_pair(e0, e1, ph, pl);
                    const uint32_t off = (uint32_t)(row * 128 + (col & 63) * 2);
                    const uint32_t sw = off ^ (uint32_t)((row & 7) << 4);
                    const int chunk = wn >> 1;
                    *(uint32_t*)(Kc + (0 * 2 + chunk) * 16384 + sw) = ph;
                    *(uint32_t*)(Kc + (1 * 2 + chunk) * 16384 + sw) = pl;
                }
            }
        CP_WAIT(0);
        __syncthreads();

        do_mma_pv(accO);
        __syncthreads();

        if (it + 1 < NKEYS / 128) {
            load_region(Kb, Khp, Klp, bn + 128);
            CP_COMMIT();
        }
    }

#pragma unroll
    for (int s = 0; s < 4; s++) {
        rs[s] += __shfl_xor_sync(0xffffffffu, rs[s], 1);
        rs[s] += __shfl_xor_sync(0xffffffffu, rs[s], 2);
    }
    if ((l & 3) == 0) {
#pragma unroll
        for (int s = 0; s < 4; s++) {
            const int row = wm * 32 + (s >> 1) * 16 + (l >> 2) + (s & 1) * 8;
            rbuf[wn * 128 + row] = rs[s];
        }
    }
    __syncthreads();

#pragma unroll
    for (int t = 0; t < 2; t++)
#pragma unroll
        for (int rh = 0; rh < 2; rh++) {
            const int row = wm * 32 + t * 16 + (l >> 2) + rh * 8;
            const float inv = 1.0f / (rbuf[row] + rbuf[128 + row] + rbuf[256 + row] + rbuf[384 + row]);
            float* orow = outp + (size_t)(bm + row) * Nn + (size_t)z * Dd;
#pragma unroll
            for (int nb = 0; nb < 4; nb++) {
                const int col = wn * 32 + nb * 8 + (l & 3) * 2;
                float2 v;
                v.x = accO[t][nb][rh * 2 + 0] * inv;
                v.y = accO[t][nb][rh * 2 + 1] * inv;
                *(float2*)(orow + col) = v;
            }
        }
}

// ---------------- prep ----------------
__global__ __launch_bounds__(256) void convert_inputs(
    const float* __restrict__ X, const float* __restrict__ cK, const float* __restrict__ cV)
{
    const size_t stride = (size_t)gridDim.x * blockDim.x;
    const size_t tid0 = (size_t)blockIdx.x * blockDim.x + threadIdx.x;

    for (size_t i = tid0; i < (size_t)Mq * Nn; i += stride) {
        bf16 h, lo;
        split_bf16(X[i], h, lo);
        g_Xh[i] = h; g_Xl[i] = lo;
    }
    const size_t nkv = (size_t)Hh * Pp * Dd;
    for (size_t i = tid0; i < nkv; i += stride) {
        const size_t h = i / ((size_t)Pp * Dd);
        const size_t r = i % ((size_t)Pp * Dd);
        const size_t o = h * (size_t)NKEYS * Dd + r;
        bf16 hh, lo;
        split_bf16(cK[i], hh, lo);
        g_Kh[o] = hh; g_Kl[o] = lo;
        split_bf16(cV[i], hh, lo);
        g_Vh[o] = hh; g_Vl[o] = lo;
    }
}

__global__ __launch_bounds__(256) void convert_W(
    const float* __restrict__ Wq, const float* __restrict__ Wk, const float* __restrict__ Wv)
{
    const int z = blockIdx.y;
    const float* W = (z == 0) ? Wq : (z == 1) ? Wk : Wv;
    bf16* oh = g_Wh + (size_t)z * Nn * Nn;
    bf16* ol = g_Wl + (size_t)z * Nn * Nn;
    const size_t n = (size_t)Nn * Nn;
    for (size_t i = (size_t)blockIdx.x * blockDim.x + threadIdx.x; i < n;
         i += (size_t)gridDim.x * blockDim.x) {
        bf16 h, lo;
        split_bf16(W[i], h, lo);
        oh[i] = h; ol[i] = lo;
    }
}

// ---------------- host launcher ----------------
extern "C" void kernel_launch(void* const* d_in, const int* in_sizes, int n_in,
                              void* d_out, int out_size)
{
    const float* X  = (const float*)d_in[0];
    const float* Wq = (const float*)d_in[1];
    const float* Wk = (const float*)d_in[2];
    const float* Wv = (const float*)d_in[3];
    const float* cK = (const float*)d_in[4];
    const float* cV = (const float*)d_in[5];
    float* out = (float*)d_out;

    bf16 *xh, *xl, *wh, *wl;
    cudaGetSymbolAddress((void**)&xh, g_Xh);
    cudaGetSymbolAddress((void**)&xl, g_Xl);
    cudaGetSymbolAddress((void**)&wh, g_Wh);
    cudaGetSymbolAddress((void**)&wl, g_Wl);

    cudaFuncSetAttribute(proj_kernel, cudaFuncAttributeMaxDynamicSharedMemorySize, SMEM_PROJ);
    cudaFuncSetAttribute(attn_kernel, cudaFuncAttributeMaxDynamicSharedMemorySize, SMEM_ATT);

    convert_inputs<<<4096, 256>>>(X, cK, cV);
    convert_W<<<dim3(4096, 3), 256>>>(Wq, Wk, Wv);

    proj_kernel<<<dim3(Nn / 128, Mq / 256, 3), 256, SMEM_PROJ>>>(xh, xl, wh, wl);

    attn_kernel<<<dim3(Mq / 128, Hh), 512, SMEM_ATT>>>(out);
}

// round 10
// speedup vs baseline: 1.1304x; 1.0239x over previous
#include <cuda_runtime.h>
#include <cuda_bf16.h>
#include <math.h>
#include <stdint.h>

#define Mq 1024
#define Nn 4096
#define Dd 128
#define Pp 3072
#define Hh 32
#define NKEYS 4096
#define NSPLIT 4
typedef __nv_bfloat16 bf16;

// ---------------- scratch ----------------
__device__ bf16 g_Xh[(size_t)Mq * Nn],       g_Xl[(size_t)Mq * Nn];
__device__ bf16 g_Wh[(size_t)3 * Nn * Nn],   g_Wl[(size_t)3 * Nn * Nn];      // natural [k][n]
__device__ bf16 g_Qh[(size_t)Hh * Mq * Dd],  g_Ql[(size_t)Hh * Mq * Dd];
__device__ bf16 g_Kh[(size_t)Hh * NKEYS * Dd], g_Kl[(size_t)Hh * NKEYS * Dd];
__device__ bf16 g_Vh[(size_t)Hh * NKEYS * Dd], g_Vl[(size_t)Hh * NKEYS * Dd];
__device__ float g_Opart[(size_t)NSPLIT * Hh * Mq * Dd];   // 64 MB partial outputs
__device__ float g_rs[(size_t)NSPLIT * Hh * Mq];           // partial row sums

// ---------------- helpers ----------------
static __device__ __forceinline__ uint32_t smem_u32(const void* p) {
    uint32_t a;
    asm("{ .reg .u64 t; cvta.to.shared.u64 t, %1; cvt.u32.u64 %0, t; }" : "=r"(a) : "l"(p));
    return a;
}
static __device__ __forceinline__ void cp_async16(uint32_t dst, const void* src) {
    asm volatile("cp.async.cg.shared.global [%0], [%1], 16;" :: "r"(dst), "l"(src));
}
#define CP_COMMIT() asm volatile("cp.async.commit_group;" ::: "memory")
#define CP_WAIT(n)  asm volatile("cp.async.wait_group %0;" :: "n"(n) : "memory")

static __device__ __forceinline__ void ldsm_x4(uint32_t& r0, uint32_t& r1, uint32_t& r2, uint32_t& r3,
                                               uint32_t addr) {
    asm volatile("ldmatrix.sync.aligned.m8n8.x4.shared.b16 {%0,%1,%2,%3}, [%4];"
                 : "=r"(r0), "=r"(r1), "=r"(r2), "=r"(r3) : "r"(addr));
}
static __device__ __forceinline__ void ldsm_x4_t(uint32_t& r0, uint32_t& r1, uint32_t& r2, uint32_t& r3,
                                                 uint32_t addr) {
    asm volatile("ldmatrix.sync.aligned.m8n8.x4.trans.shared.b16 {%0,%1,%2,%3}, [%4];"
                 : "=r"(r0), "=r"(r1), "=r"(r2), "=r"(r3) : "r"(addr));
}
static __device__ __forceinline__ void mma_bf16(float* c, const uint32_t* a, const uint32_t* b) {
    asm volatile(
        "mma.sync.aligned.m16n8k16.row.col.f32.bf16.bf16.f32 "
        "{%0,%1,%2,%3}, {%4,%5,%6,%7}, {%8,%9}, {%0,%1,%2,%3};"
        : "+f"(c[0]), "+f"(c[1]), "+f"(c[2]), "+f"(c[3])
        : "r"(a[0]), "r"(a[1]), "r"(a[2]), "r"(a[3]), "r"(b[0]), "r"(b[1]));
}
static __device__ __forceinline__ void split_bf16(float v, bf16& h, bf16& l) {
    h = __float2bfloat16(v);
    l = __float2bfloat16(v - __bfloat162float(h));
}
static __device__ __forceinline__ uint32_t cvt_bf16x2(float a, float b) {
    uint32_t r;
    asm("cvt.rn.bf16x2.f32 %0, %1, %2;" : "=r"(r) : "f"(b), "f"(a));
    return r;
}
static __device__ __forceinline__ void split_pair(float v0, float v1, uint32_t& ph, uint32_t& pl) {
    ph = cvt_bf16x2(v0, v1);
    const float h0 = __uint_as_float(ph << 16);
    const float h1 = __uint_as_float(ph & 0xFFFF0000u);
    pl = cvt_bf16x2(v0 - h0, v1 - h1);
}

#define PROJ_STAGE 98304
#define SMEM_PROJ (2048 + 2 * PROJ_STAGE)
#define SMEM_ATT  (2048 + 3 * 4 * 16384)

// ---------------- projection GEMM: TM=256, TN=128, 256 threads (R9, unchanged) ----------------
__global__ __launch_bounds__(256, 1) void proj_kernel(
    const bf16* __restrict__ Xh, const bf16* __restrict__ Xl,
    const bf16* __restrict__ Wh, const bf16* __restrict__ Wl)
{
    extern __shared__ char smem[];
    float* rbuf = (float*)smem;
    const uint32_t sb = smem_u32(smem);
    const int tid = threadIdx.x;
    const int wid = tid >> 5, l = tid & 31;
    const int wm = wid >> 1, wn = wid & 1;
    const int bn = blockIdx.x * 128, bm = blockIdx.y * 256, z = blockIdx.z;

    const bf16* WhP = Wh + (size_t)z * Nn * Nn;
    const bf16* WlP = Wl + (size_t)z * Nn * Nn;

    float acc[4][8][4];
#pragma unroll
    for (int t = 0; t < 4; t++)
#pragma unroll
        for (int nb = 0; nb < 8; nb++)
#pragma unroll
            for (int i = 0; i < 4; i++) acc[t][nb][i] = 0.f;

    const int nch = Nn >> 6;

    auto load_chunk = [&](int c) {
        const uint32_t stb = sb + 2048 + (c & 1) * PROJ_STAGE;
        const int k0 = c << 6;
#pragma unroll
        for (int p = 0; p < 2; p++) {
            const bf16* src = p ? Xl : Xh;
#pragma unroll
            for (int i = tid; i < 2048; i += 256) {
                const int row = i >> 3, cc = i & 7;
                const uint32_t off = (uint32_t)(row * 128 + cc * 16);
                cp_async16(stb + p * 32768 + (off ^ (uint32_t)((row & 7) << 4)),
                           src + (size_t)(bm + row) * Nn + k0 + cc * 8);
            }
        }
#pragma unroll
        for (int p = 0; p < 2; p++) {
            const bf16* src = p ? WlP : WhP;
#pragma unroll
            for (int i = tid; i < 1024; i += 256) {
                const int row = i >> 4, c16 = i & 15;
                const uint32_t off = (uint32_t)(row * 256 + c16 * 16);
                cp_async16(stb + 65536 + p * 16384 + (off ^ (uint32_t)((row & 7) << 4)),
                           src + (size_t)(k0 + row) * Nn + bn + c16 * 8);
            }
        }
        CP_COMMIT();
    };

    load_chunk(0);
    load_chunk(1);

    for (int c = 0; c < nch; c++) {
        if (c + 1 < nch) { CP_WAIT(1); } else { CP_WAIT(0); }
        __syncthreads();
        const uint32_t stb = sb + 2048 + (c & 1) * PROJ_STAGE;

#pragma unroll
        for (int kk = 0; kk < 4; kk++) {
            uint32_t bH[8][2], bL[8][2];
#pragma unroll
            for (int bt = 0; bt < 4; bt++) {
                const int krow = kk * 16 + (l & 7) + ((l >> 3) & 1) * 8;
                const int colb = wn * 128 + bt * 32 + ((l >> 4) & 1) * 16;
                const uint32_t bo = (uint32_t)(krow * 256) + (uint32_t)(colb ^ ((krow & 7) << 4));
                ldsm_x4_t(bH[2 * bt][0], bH[2 * bt][1], bH[2 * bt + 1][0], bH[2 * bt + 1][1],
                          stb + 65536 + bo);
                ldsm_x4_t(bL[2 * bt][0], bL[2 * bt][1], bL[2 * bt + 1][0], bL[2 * bt + 1][1],
                          stb + 65536 + 16384 + bo);
            }
#pragma unroll
            for (int t = 0; t < 4; t++) {
                uint32_t aH[4], aL[4];
                const int mrow = wm * 64 + t * 16 + (l & 7) + ((l >> 3) & 1) * 8;
                const int kb = kk * 32 + ((l >> 4) & 1) * 16;
                const uint32_t ao = (uint32_t)(mrow * 128) + (uint32_t)(kb ^ ((mrow & 7) << 4));
                ldsm_x4(aH[0], aH[1], aH[2], aH[3], stb + ao);
                ldsm_x4(aL[0], aL[1], aL[2], aL[3], stb + 32768 + ao);
#pragma unroll
                for (int nb = 0; nb < 8; nb++) {
                    mma_bf16(acc[t][nb], aH, bH[nb]);
                    mma_bf16(acc[t][nb], aH, bL[nb]);
                    mma_bf16(acc[t][nb], aL, bH[nb]);
                }
            }
        }
        __syncthreads();
        if (c + 2 < nch) load_chunk(c + 2);
    }

    if (z < 2) {
        float ss[8];
#pragma unroll
        for (int s = 0; s < 8; s++) ss[s] = 0.f;
#pragma unroll
        for (int t = 0; t < 4; t++)
#pragma unroll
            for (int nb = 0; nb < 8; nb++)
#pragma unroll
                for (int i = 0; i < 4; i++) {
                    const float v = acc[t][nb][i];
                    ss[t * 2 + (i >> 1)] += v * v;
                }
#pragma unroll
        for (int s = 0; s < 8; s++) {
            ss[s] += __shfl_xor_sync(0xffffffffu, ss[s], 1);
            ss[s] += __shfl_xor_sync(0xffffffffu, ss[s], 2);
        }
        if ((l & 3) == 0) {
#pragma unroll
            for (int s = 0; s < 8; s++) {
                const int row = wm * 64 + (s >> 1) * 16 + (l >> 2) + (s & 1) * 8;
                rbuf[wn * 256 + row] = ss[s];
            }
        }
        __syncthreads();
    }

    bf16* dh = (z == 0) ? g_Qh : (z == 1) ? g_Kh : g_Vh;
    bf16* dl = (z == 0) ? g_Ql : (z == 1) ? g_Kl : g_Vl;
#pragma unroll
    for (int t = 0; t < 4; t++)
#pragma unroll
        for (int rh = 0; rh < 2; rh++) {
            const int row = wm * 64 + t * 16 + (l >> 2) + rh * 8;
            float sc = 1.0f;
            if (z < 2) sc = rsqrtf((rbuf[row] + rbuf[256 + row]) * (1.0f / 128.0f));
            const size_t rowbase = (z == 0)
                ? ((size_t)blockIdx.x * Mq + bm + row) * 128
                : ((size_t)blockIdx.x * NKEYS + Pp + bm + row) * 128;
#pragma unroll
            for (int nb = 0; nb < 8; nb++) {
                const int col = wn * 64 + nb * 8 + (l & 3) * 2;
                uint32_t ph, pl;
                split_pair(acc[t][nb][rh * 2 + 0] * sc, acc[t][nb][rh * 2 + 1] * sc, ph, pl);
                *(uint32_t*)(dh + rowbase + col) = ph;
                *(uint32_t*)(dl + rowbase + col) = pl;
            }
        }
}

// ---------------- fused flash attention, split-KV (grid.z = split) ----------------
__global__ __launch_bounds__(512, 1) void attn_kernel()
{
    extern __shared__ char smem[];
    float* rbuf = (float*)smem;
    const uint32_t sb = smem_u32(smem);
    const uint32_t Qb = sb + 2048;
    const uint32_t Kb = Qb + 65536;
    const uint32_t Vb = Kb + 65536;
    char* Kc = smem + 2048 + 65536;

    const int tid = threadIdx.x;
    const int wid = tid >> 5, l = tid & 31;
    const int wm = wid >> 2, wn = wid & 3;
    const int bm = blockIdx.x * 128;
    const int z = blockIdx.y;
    const int sp = blockIdx.z;
    const int key0 = sp * (NKEYS / NSPLIT);

    const bf16* Qhp = g_Qh + ((size_t)z * Mq + bm) * Dd;
    const bf16* Qlp = g_Ql + ((size_t)z * Mq + bm) * Dd;
    const bf16* Khp = g_Kh + (size_t)z * NKEYS * Dd;
    const bf16* Klp = g_Kl + (size_t)z * NKEYS * Dd;
    const bf16* Vhp = g_Vh + (size_t)z * NKEYS * Dd;
    const bf16* Vlp = g_Vl + (size_t)z * NKEYS * Dd;

    auto load_region = [&](uint32_t dstb, const bf16* srcH, const bf16* srcL, int row0) {
#pragma unroll
        for (int p = 0; p < 4; p++) {
            const bf16* src = (p < 2) ? srcH : srcL;
            const int k0 = (p & 1) * 64;
#pragma unroll
            for (int i = tid; i < 1024; i += 512) {
                const int row = i >> 3, cc = i & 7;
                const uint32_t off = (uint32_t)(row * 128 + cc * 16);
                cp_async16(dstb + p * 16384 + (off ^ (uint32_t)((row & 7) << 4)),
                           src + (size_t)(row0 + row) * Dd + k0 + cc * 8);
            }
        }
    };
    auto load_v = [&](int bn) {
#pragma unroll
        for (int p = 0; p < 2; p++) {
            const bf16* src = p ? Vlp : Vhp;
#pragma unroll
            for (int i = tid; i < 2048; i += 512) {
                const int row = i >> 4, c16 = i & 15;
                const uint32_t off = (uint32_t)(row * 256 + c16 * 16);
                cp_async16(Vb + p * 32768 + (off ^ (uint32_t)((row & 7) << 4)),
                           src + (size_t)(bn + row) * Dd + c16 * 8);
            }
        }
    };

    auto do_mma_qk = [&](float acc[2][4][4]) {
#pragma unroll
        for (int c = 0; c < 2; c++) {
            const uint32_t aHb = Qb + c * 16384, aLb = Qb + (2 + c) * 16384;
            const uint32_t bHb = Kb + c * 16384, bLb = Kb + (2 + c) * 16384;
#pragma unroll
            for (int kk = 0; kk < 4; kk++) {
                uint32_t aH[2][4], aL[2][4];
#pragma unroll
                for (int t = 0; t < 2; t++) {
                    const int mrow = wm * 32 + t * 16 + (l & 7) + ((l >> 3) & 1) * 8;
                    const int kb = kk * 32 + ((l >> 4) & 1) * 16;
                    const uint32_t ao = (uint32_t)(mrow * 128) + (uint32_t)(kb ^ ((mrow & 7) << 4));
                    ldsm_x4(aH[t][0], aH[t][1], aH[t][2], aH[t][3], aHb + ao);
                    ldsm_x4(aL[t][0], aL[t][1], aL[t][2], aL[t][3], aLb + ao);
                }
                uint32_t bH[4][2], bL[4][2];
#pragma unroll
                for (int bt = 0; bt < 2; bt++) {
                    const int nrow = wn * 32 + bt * 16 + (l & 7) + ((l >> 4) & 1) * 8;
                    const int kb = kk * 32 + ((l >> 3) & 1) * 16;
                    const uint32_t bo = (uint32_t)(nrow * 128) + (uint32_t)(kb ^ ((nrow & 7) << 4));
                    ldsm_x4(bH[2 * bt][0], bH[2 * bt][1], bH[2 * bt + 1][0], bH[2 * bt + 1][1], bHb + bo);
                    ldsm_x4(bL[2 * bt][0], bL[2 * bt][1], bL[2 * bt + 1][0], bL[2 * bt + 1][1], bLb + bo);
                }
#pragma unroll
                for (int t = 0; t < 2; t++)
#pragma unroll
                    for (int nb = 0; nb < 4; nb++) {
                        mma_bf16(acc[t][nb], aH[t], bH[nb]);
                        mma_bf16(acc[t][nb], aH[t], bL[nb]);
                        mma_bf16(acc[t][nb], aL[t], bH[nb]);
                    }
            }
        }
    };

    auto do_mma_pv = [&](float acc[2][4][4]) {
#pragma unroll
        for (int c = 0; c < 2; c++) {
            const uint32_t aHb = Kb + c * 16384, aLb = Kb + (2 + c) * 16384;
#pragma unroll
            for (int kk = 0; kk < 4; kk++) {
                uint32_t aH[2][4], aL[2][4];
#pragma unroll
                for (int t = 0; t < 2; t++) {
                    const int mrow = wm * 32 + t * 16 + (l & 7) + ((l >> 3) & 1) * 8;
                    const int kb = kk * 32 + ((l >> 4) & 1) * 16;
                    const uint32_t ao = (uint32_t)(mrow * 128) + (uint32_t)(kb ^ ((mrow & 7) << 4));
                    ldsm_x4(aH[t][0], aH[t][1], aH[t][2], aH[t][3], aHb + ao);
                    ldsm_x4(aL[t][0], aL[t][1], aL[t][2], aL[t][3], aLb + ao);
                }
                uint32_t bH[4][2], bL[4][2];
#pragma unroll
                for (int bt = 0; bt < 2; bt++) {
                    const int key = c * 64 + kk * 16 + (l & 7) + ((l >> 3) & 1) * 8;
                    const int colb = wn * 64 + bt * 32 + ((l >> 4) & 1) * 16;
                    const uint32_t bo = (uint32_t)(key * 256) + (uint32_t)(colb ^ ((key & 7) << 4));
                    ldsm_x4_t(bH[2 * bt][0], bH[2 * bt][1], bH[2 * bt + 1][0], bH[2 * bt + 1][1],
                              Vb + 0 * 32768 + bo);
                    ldsm_x4_t(bL[2 * bt][0], bL[2 * bt][1], bL[2 * bt + 1][0], bL[2 * bt + 1][1],
                              Vb + 1 * 32768 + bo);
                }
#pragma unroll
                for (int t = 0; t < 2; t++)
#pragma unroll
                    for (int nb = 0; nb < 4; nb++) {
                        mma_bf16(acc[t][nb], aH[t], bH[nb]);
                        mma_bf16(acc[t][nb], aH[t], bL[nb]);
                        mma_bf16(acc[t][nb], aL[t], bH[nb]);
                    }
            }
        }
    };

    float accO[2][4][4];
#pragma unroll
    for (int t = 0; t < 2; t++)
#pragma unroll
        for (int nb = 0; nb < 4; nb++)
#pragma unroll
            for (int i = 0; i < 4; i++) accO[t][nb][i] = 0.f;
    float rs[4] = {0.f, 0.f, 0.f, 0.f};

    load_region(Qb, Qhp, Qlp, 0);
    load_region(Kb, Khp, Klp, key0);
    CP_COMMIT();

    const int NIT = (NKEYS / NSPLIT) / 128;   // 8
    for (int it = 0; it < NIT; it++) {
        const int bn = key0 + it * 128;
        load_v(bn);
        CP_COMMIT();

        CP_WAIT(1);
        __syncthreads();

        float accS[2][4][4];
#pragma unroll
        for (int t = 0; t < 2; t++)
#pragma unroll
            for (int nb = 0; nb < 4; nb++)
#pragma unroll
                for (int i = 0; i < 4; i++) accS[t][nb][i] = 0.f;

        do_mma_qk(accS);
        __syncthreads();

#pragma unroll
        for (int t = 0; t < 2; t++)
#pragma unroll
            for (int rh = 0; rh < 2; rh++) {
                const int row = wm * 32 + t * 16 + (l >> 2) + rh * 8;
#pragma unroll
                for (int nb = 0; nb < 4; nb++) {
                    const int col = wn * 32 + nb * 8 + (l & 3) * 2;
                    const float e0 = __expf(accS[t][nb][rh * 2 + 0]);
                    const float e1 = __expf(accS[t][nb][rh * 2 + 1]);
                    rs[t * 2 + rh] += e0 + e1;
                    uint32_t ph, pl;
                    split_pair(e0, e1, ph, pl);
                    const uint32_t off = (uint32_t)(row * 128 + (col & 63) * 2);
                    const uint32_t sw = off ^ (uint32_t)((row & 7) << 4);
                    const int chunk = wn >> 1;
                    *(uint32_t*)(Kc + (0 * 2 + chunk) * 16384 + sw) = ph;
                    *(uint32_t*)(Kc + (1 * 2 + chunk) * 16384 + sw) = pl;
                }
            }
        CP_WAIT(0);
        __syncthreads();

        do_mma_pv(accO);
        __syncthreads();

        if (it + 1 < NIT) {
            load_region(Kb, Khp, Klp, bn + 128);
            CP_COMMIT();
        }
    }

    // reduce row sums across quads + n-warps
#pragma unroll
    for (int s = 0; s < 4; s++) {
        rs[s] += __shfl_xor_sync(0xffffffffu, rs[s], 1);
        rs[s] += __shfl_xor_sync(0xffffffffu, rs[s], 2);
    }
    if ((l & 3) == 0) {
#pragma unroll
        for (int s = 0; s < 4; s++) {
            const int row = wm * 32 + (s >> 1) * 16 + (l >> 2) + (s & 1) * 8;
            rbuf[wn * 128 + row] = rs[s];
        }
    }
    __syncthreads();

    if (tid < 128) {
        g_rs[((size_t)sp * Hh + z) * Mq + bm + tid] =
            rbuf[tid] + rbuf[128 + tid] + rbuf[256 + tid] + rbuf[384 + tid];
    }

    float* obase = g_Opart + (((size_t)sp * Hh + z) * Mq + bm) * Dd;
#pragma unroll
    for (int t = 0; t < 2; t++)
#pragma unroll
        for (int rh = 0; rh < 2; rh++) {
            const int row = wm * 32 + t * 16 + (l >> 2) + rh * 8;
#pragma unroll
            for (int nb = 0; nb < 4; nb++) {
                const int col = wn * 32 + nb * 8 + (l & 3) * 2;
                float2 v;
                v.x = accO[t][nb][rh * 2 + 0];
                v.y = accO[t][nb][rh * 2 + 1];
                *(float2*)(obase + (size_t)row * Dd + col) = v;
            }
        }
}

// ---------------- combine partials -> out ----------------
__global__ __launch_bounds__(256) void combine_kernel(float* __restrict__ outp)
{
    const size_t idx = (size_t)blockIdx.x * blockDim.x + threadIdx.x;   // over Mq*Nn/4
    const size_t e = idx * 4;
    const int m = (int)(e >> 12);          // e / Nn
    const int c = (int)(e & (Nn - 1));
    const int h = c >> 7;
    const int d = c & 127;

    const size_t rbase = (size_t)h * Mq + m;
    const float tot = g_rs[rbase] + g_rs[(size_t)Hh * Mq + rbase]
                    + g_rs[2 * (size_t)Hh * Mq + rbase] + g_rs[3 * (size_t)Hh * Mq + rbase];
    const float inv = 1.0f / tot;

    const size_t pbase = ((size_t)h * Mq + m) * Dd + d;
    const size_t pstep = (size_t)Hh * Mq * Dd;
    float4 a = *(const float4*)(g_Opart + pbase);
    float4 b = *(const float4*)(g_Opart + pbase + pstep);
    float4 cc = *(const float4*)(g_Opart + pbase + 2 * pstep);
    float4 dd = *(const float4*)(g_Opart + pbase + 3 * pstep);
    float4 o;
    o.x = (a.x + b.x + cc.x + dd.x) * inv;
    o.y = (a.y + b.y + cc.y + dd.y) * inv;
    o.z = (a.z + b.z + cc.z + dd.z) * inv;
    o.w = (a.w + b.w + cc.w + dd.w) * inv;
    *(float4*)(outp + e) = o;
}

// ---------------- prep ----------------
__global__ __launch_bounds__(256) void convert_inputs(
    const float* __restrict__ X, const float* __restrict__ cK, const float* __restrict__ cV)
{
    const size_t stride = (size_t)gridDim.x * blockDim.x;
    const size_t tid0 = (size_t)blockIdx.x * blockDim.x + threadIdx.x;

    for (size_t i = tid0; i < (size_t)Mq * Nn; i += stride) {
        bf16 h, lo;
        split_bf16(X[i], h, lo);
        g_Xh[i] = h; g_Xl[i] = lo;
    }
    const size_t nkv = (size_t)Hh * Pp * Dd;
    for (size_t i = tid0; i < nkv; i += stride) {
        const size_t h = i / ((size_t)Pp * Dd);
        const size_t r = i % ((size_t)Pp * Dd);
        const size_t o = h * (size_t)NKEYS * Dd + r;
        bf16 hh, lo;
        split_bf16(cK[i], hh, lo);
        g_Kh[o] = hh; g_Kl[o] = lo;
        split_bf16(cV[i], hh, lo);
        g_Vh[o] = hh; g_Vl[o] = lo;
    }
}

__global__ __launch_bounds__(256) void convert_W(
    const float* __restrict__ Wq, const float* __restrict__ Wk, const float* __restrict__ Wv)
{
    const int z = blockIdx.y;
    const float* W = (z == 0) ? Wq : (z == 1) ? Wk : Wv;
    bf16* oh = g_Wh + (size_t)z * Nn * Nn;
    bf16* ol = g_Wl + (size_t)z * Nn * Nn;
    const size_t n = (size_t)Nn * Nn;
    for (size_t i = (size_t)blockIdx.x * blockDim.x + threadIdx.x; i < n;
         i += (size_t)gridDim.x * blockDim.x) {
        bf16 h, lo;
        split_bf16(W[i], h, lo);
        oh[i] = h; ol[i] = lo;
    }
}

// ---------------- host launcher ----------------
extern "C" void kernel_launch(void* const* d_in, const int* in_sizes, int n_in,
                              void* d_out, int out_size)
{
    const float* X  = (const float*)d_in[0];
    const float* Wq = (const float*)d_in[1];
    const float* Wk = (const float*)d_in[2];
    const float* Wv = (const float*)d_in[3];
    const float* cK = (const float*)d_in[4];
    const float* cV = (const float*)d_in[5];
    float* out = (float*)d_out;

    bf16 *xh, *xl, *wh, *wl;
    cudaGetSymbolAddress((void**)&xh, g_Xh);
    cudaGetSymbolAddress((void**)&xl, g_Xl);
    cudaGetSymbolAddress((void**)&wh, g_Wh);
    cudaGetSymbolAddress((void**)&wl, g_Wl);

    cudaFuncSetAttribute(proj_kernel, cudaFuncAttributeMaxDynamicSharedMemorySize, SMEM_PROJ);
    cudaFuncSetAttribute(attn_kernel, cudaFuncAttributeMaxDynamicSharedMemorySize, SMEM_ATT);

    convert_inputs<<<4096, 256>>>(X, cK, cV);
    convert_W<<<dim3(4096, 3), 256>>>(Wq, Wk, Wv);

    proj_kernel<<<dim3(Nn / 128, Mq / 256, 3), 256, SMEM_PROJ>>>(xh, xl, wh, wl);

    attn_kernel<<<dim3(Mq / 128, Hh, NSPLIT), 512, SMEM_ATT>>>();

    combine_kernel<<<(Mq * Nn / 4) / 256, 256>>>(out);
}

// round 11
// speedup vs baseline: 1.1373x; 1.0061x over previous
#include <cuda_runtime.h>
#include <cuda_bf16.h>
#include <math.h>
#include <stdint.h>

#define Mq 1024
#define Nn 4096
#define Dd 128
#define Pp 3072
#define Hh 32
#define NKEYS 4096
#define NSPLIT 4
#define KEYB 64
#define NIT ((NKEYS / NSPLIT) / KEYB)   // 16
typedef __nv_bfloat16 bf16;

// ---------------- scratch ----------------
__device__ bf16 g_Xh[(size_t)Mq * Nn],       g_Xl[(size_t)Mq * Nn];
__device__ bf16 g_Wh[(size_t)3 * Nn * Nn],   g_Wl[(size_t)3 * Nn * Nn];      // natural [k][n]
__device__ bf16 g_Qh[(size_t)Hh * Mq * Dd],  g_Ql[(size_t)Hh * Mq * Dd];
__device__ bf16 g_Kh[(size_t)Hh * NKEYS * Dd], g_Kl[(size_t)Hh * NKEYS * Dd];
__device__ bf16 g_Vh[(size_t)Hh * NKEYS * Dd], g_Vl[(size_t)Hh * NKEYS * Dd];
__device__ float g_Opart[(size_t)NSPLIT * Hh * Mq * Dd];
__device__ float g_rs[(size_t)NSPLIT * Hh * Mq];

// ---------------- helpers ----------------
static __device__ __forceinline__ uint32_t smem_u32(const void* p) {
    uint32_t a;
    asm("{ .reg .u64 t; cvta.to.shared.u64 t, %1; cvt.u32.u64 %0, t; }" : "=r"(a) : "l"(p));
    return a;
}
static __device__ __forceinline__ void cp_async16(uint32_t dst, const void* src) {
    asm volatile("cp.async.cg.shared.global [%0], [%1], 16;" :: "r"(dst), "l"(src));
}
#define CP_COMMIT() asm volatile("cp.async.commit_group;" ::: "memory")
#define CP_WAIT(n)  asm volatile("cp.async.wait_group %0;" :: "n"(n) : "memory")

static __device__ __forceinline__ void ldsm_x4(uint32_t& r0, uint32_t& r1, uint32_t& r2, uint32_t& r3,
                                               uint32_t addr) {
    asm volatile("ldmatrix.sync.aligned.m8n8.x4.shared.b16 {%0,%1,%2,%3}, [%4];"
                 : "=r"(r0), "=r"(r1), "=r"(r2), "=r"(r3) : "r"(addr));
}
static __device__ __forceinline__ void ldsm_x4_t(uint32_t& r0, uint32_t& r1, uint32_t& r2, uint32_t& r3,
                                                 uint32_t addr) {
    asm volatile("ldmatrix.sync.aligned.m8n8.x4.trans.shared.b16 {%0,%1,%2,%3}, [%4];"
                 : "=r"(r0), "=r"(r1), "=r"(r2), "=r"(r3) : "r"(addr));
}
static __device__ __forceinline__ void mma_bf16(float* c, const uint32_t* a, const uint32_t* b) {
    asm volatile(
        "mma.sync.aligned.m16n8k16.row.col.f32.bf16.bf16.f32 "
        "{%0,%1,%2,%3}, {%4,%5,%6,%7}, {%8,%9}, {%0,%1,%2,%3};"
        : "+f"(c[0]), "+f"(c[1]), "+f"(c[2]), "+f"(c[3])
        : "r"(a[0]), "r"(a[1]), "r"(a[2]), "r"(a[3]), "r"(b[0]), "r"(b[1]));
}
static __device__ __forceinline__ void split_bf16(float v, bf16& h, bf16& l) {
    h = __float2bfloat16(v);
    l = __float2bfloat16(v - __bfloat162float(h));
}
static __device__ __forceinline__ uint32_t cvt_bf16x2(float a, float b) {
    uint32_t r;
    asm("cvt.rn.bf16x2.f32 %0, %1, %2;" : "=r"(r) : "f"(b), "f"(a));
    return r;
}
static __device__ __forceinline__ void split_pair(float v0, float v1, uint32_t& ph, uint32_t& pl) {
    ph = cvt_bf16x2(v0, v1);
    const float h0 = __uint_as_float(ph << 16);
    const float h1 = __uint_as_float(ph & 0xFFFF0000u);
    pl = cvt_bf16x2(v0 - h0, v1 - h1);
}

#define PROJ_STAGE 98304
#define SMEM_PROJ (2048 + 2 * PROJ_STAGE)
// attn: rbuf 2048 | Q 64K | K ring 2x32K | V ring 2x32K | P 32K  = 231424 B
#define SMEM_ATT  (2048 + 65536 + 65536 + 65536 + 32768)

// ---------------- projection GEMM: TM=256, TN=128, 256 threads (R9/R10, unchanged) ----------------
__global__ __launch_bounds__(256, 1) void proj_kernel(
    const bf16* __restrict__ Xh, const bf16* __restrict__ Xl,
    const bf16* __restrict__ Wh, const bf16* __restrict__ Wl)
{
    extern __shared__ char smem[];
    float* rbuf = (float*)smem;
    const uint32_t sb = smem_u32(smem);
    const int tid = threadIdx.x;
    const int wid = tid >> 5, l = tid & 31;
    const int wm = wid >> 1, wn = wid & 1;
    const int bn = blockIdx.x * 128, bm = blockIdx.y * 256, z = blockIdx.z;

    const bf16* WhP = Wh + (size_t)z * Nn * Nn;
    const bf16* WlP = Wl + (size_t)z * Nn * Nn;

    float acc[4][8][4];
#pragma unroll
    for (int t = 0; t < 4; t++)
#pragma unroll
        for (int nb = 0; nb < 8; nb++)
#pragma unroll
            for (int i = 0; i < 4; i++) acc[t][nb][i] = 0.f;

    const int nch = Nn >> 6;

    auto load_chunk = [&](int c) {
        const uint32_t stb = sb + 2048 + (c & 1) * PROJ_STAGE;
        const int k0 = c << 6;
#pragma unroll
        for (int p = 0; p < 2; p++) {
            const bf16* src = p ? Xl : Xh;
#pragma unroll
            for (int i = tid; i < 2048; i += 256) {
                const int row = i >> 3, cc = i & 7;
                const uint32_t off = (uint32_t)(row * 128 + cc * 16);
                cp_async16(stb + p * 32768 + (off ^ (uint32_t)((row & 7) << 4)),
                           src + (size_t)(bm + row) * Nn + k0 + cc * 8);
            }
        }
#pragma unroll
        for (int p = 0; p < 2; p++) {
            const bf16* src = p ? WlP : WhP;
#pragma unroll
            for (int i = tid; i < 1024; i += 256) {
                const int row = i >> 4, c16 = i & 15;
                const uint32_t off = (uint32_t)(row * 256 + c16 * 16);
                cp_async16(stb + 65536 + p * 16384 + (off ^ (uint32_t)((row & 7) << 4)),
                           src + (size_t)(k0 + row) * Nn + bn + c16 * 8);
            }
        }
        CP_COMMIT();
    };

    load_chunk(0);
    load_chunk(1);

    for (int c = 0; c < nch; c++) {
        if (c + 1 < nch) { CP_WAIT(1); } else { CP_WAIT(0); }
        __syncthreads();
        const uint32_t stb = sb + 2048 + (c & 1) * PROJ_STAGE;

#pragma unroll
        for (int kk = 0; kk < 4; kk++) {
            uint32_t bH[8][2], bL[8][2];
#pragma unroll
            for (int bt = 0; bt < 4; bt++) {
                const int krow = kk * 16 + (l & 7) + ((l >> 3) & 1) * 8;
                const int colb = wn * 128 + bt * 32 + ((l >> 4) & 1) * 16;
                const uint32_t bo = (uint32_t)(krow * 256) + (uint32_t)(colb ^ ((krow & 7) << 4));
                ldsm_x4_t(bH[2 * bt][0], bH[2 * bt][1], bH[2 * bt + 1][0], bH[2 * bt + 1][1],
                          stb + 65536 + bo);
                ldsm_x4_t(bL[2 * bt][0], bL[2 * bt][1], bL[2 * bt + 1][0], bL[2 * bt + 1][1],
                          stb + 65536 + 16384 + bo);
            }
#pragma unroll
            for (int t = 0; t < 4; t++) {
                uint32_t aH[4], aL[4];
                const int mrow = wm * 64 + t * 16 + (l & 7) + ((l >> 3) & 1) * 8;
                const int kb = kk * 32 + ((l >> 4) & 1) * 16;
                const uint32_t ao = (uint32_t)(mrow * 128) + (uint32_t)(kb ^ ((mrow & 7) << 4));
                ldsm_x4(aH[0], aH[1], aH[2], aH[3], stb + ao);
                ldsm_x4(aL[0], aL[1], aL[2], aL[3], stb + 32768 + ao);
#pragma unroll
                for (int nb = 0; nb < 8; nb++) {
                    mma_bf16(acc[t][nb], aH, bH[nb]);
                    mma_bf16(acc[t][nb], aH, bL[nb]);
                    mma_bf16(acc[t][nb], aL, bH[nb]);
                }
            }
        }
        __syncthreads();
        if (c + 2 < nch) load_chunk(c + 2);
    }

    if (z < 2) {
        float ss[8];
#pragma unroll
        for (int s = 0; s < 8; s++) ss[s] = 0.f;
#pragma unroll
        for (int t = 0; t < 4; t++)
#pragma unroll
            for (int nb = 0; nb < 8; nb++)
#pragma unroll
                for (int i = 0; i < 4; i++) {
                    const float v = acc[t][nb][i];
                    ss[t * 2 + (i >> 1)] += v * v;
                }
#pragma unroll
        for (int s = 0; s < 8; s++) {
            ss[s] += __shfl_xor_sync(0xffffffffu, ss[s], 1);
            ss[s] += __shfl_xor_sync(0xffffffffu, ss[s], 2);
        }
        if ((l & 3) == 0) {
#pragma unroll
            for (int s = 0; s < 8; s++) {
                const int row = wm * 64 + (s >> 1) * 16 + (l >> 2) + (s & 1) * 8;
                rbuf[wn * 256 + row] = ss[s];
            }
        }
        __syncthreads();
    }

    bf16* dh = (z == 0) ? g_Qh : (z == 1) ? g_Kh : g_Vh;
    bf16* dl = (z == 0) ? g_Ql : (z == 1) ? g_Kl : g_Vl;
#pragma unroll
    for (int t = 0; t < 4; t++)
#pragma unroll
        for (int rh = 0; rh < 2; rh++) {
            const int row = wm * 64 + t * 16 + (l >> 2) + rh * 8;
            float sc = 1.0f;
            if (z < 2) sc = rsqrtf((rbuf[row] + rbuf[256 + row]) * (1.0f / 128.0f));
            const size_t rowbase = (z == 0)
                ? ((size_t)blockIdx.x * Mq + bm + row) * 128
                : ((size_t)blockIdx.x * NKEYS + Pp + bm + row) * 128;
#pragma unroll
            for (int nb = 0; nb < 8; nb++) {
                const int col = wn * 64 + nb * 8 + (l & 3) * 2;
                uint32_t ph, pl;
                split_pair(acc[t][nb][rh * 2 + 0] * sc, acc[t][nb][rh * 2 + 1] * sc, ph, pl);
                *(uint32_t*)(dh + rowbase + col) = ph;
                *(uint32_t*)(dl + rowbase + col) = pl;
            }
        }
}

// ---------------- fused flash attention, split-KV, 64-key iterations ----------------
__global__ __launch_bounds__(512, 1) void attn_kernel()
{
    extern __shared__ char smem[];
    float* rbuf = (float*)smem;
    const uint32_t sb = smem_u32(smem);
    const uint32_t Qb = sb + 2048;
    const uint32_t Kr = Qb + 65536;           // 2 x 32KB buffers
    const uint32_t Vr = Kr + 65536;           // 2 x 32KB buffers
    const uint32_t Pb = Vr + 65536;           // 32KB (H @0, L @16384)

    const int tid = threadIdx.x;
    const int wid = tid >> 5, l = tid & 31;
    const int wm = wid >> 2, wn = wid & 3;
    const int bm = blockIdx.x * 128;
    const int z = blockIdx.y;
    const int sp = blockIdx.z;
    const int key0 = sp * (NKEYS / NSPLIT);

    const bf16* Qhp = g_Qh + ((size_t)z * Mq + bm) * Dd;
    const bf16* Qlp = g_Ql + ((size_t)z * Mq + bm) * Dd;
    const bf16* Khp = g_Kh + (size_t)z * NKEYS * Dd;
    const bf16* Klp = g_Kl + (size_t)z * NKEYS * Dd;
    const bf16* Vhp = g_Vh + (size_t)z * NKEYS * Dd;
    const bf16* Vlp = g_Vl + (size_t)z * NKEYS * Dd;

    // Q: 4 planes [128m][128B]: 0=H d0-63, 1=H d64-127, 2=L d0-63, 3=L d64-127
    auto load_Q = [&]() {
#pragma unroll
        for (int j = 0; j < 8; j++) {
            const int i = tid + j * 512;
            const int plane = i >> 10, row = (i >> 3) & 127, cc = i & 7;
            const bf16* src = (plane < 2) ? Qhp : Qlp;
            const int k0 = (plane & 1) * 64;
            const uint32_t off = (uint32_t)(row * 128 + cc * 16);
            cp_async16(Qb + plane * 16384 + (off ^ (uint32_t)((row & 7) << 4)),
                       src + (size_t)row * Dd + k0 + cc * 8);
        }
    };
    // K buffer (32KB): plane p (0=Hd0,1=Hd64,2=Ld0,3=Ld64), each [64keys][128B]
    auto load_K = [&](int buf, int krow0) {
#pragma unroll
        for (int j = 0; j < 4; j++) {
            const int i = tid + j * 512;
            const int plane = i >> 9, row = (i >> 3) & 63, cc = i & 7;
            const bf16* src = (plane < 2) ? Khp : Klp;
            const int k0 = (plane & 1) * 64;
            const uint32_t off = (uint32_t)(row * 128 + cc * 16);
            cp_async16(Kr + buf * 32768 + plane * 8192 + (off ^ (uint32_t)((row & 7) << 4)),
                       src + (size_t)(krow0 + row) * Dd + k0 + cc * 8);
        }
    };
    // V buffer (32KB): plane 0=H, 1=L, each [64keys][256B]
    auto load_V = [&](int buf, int krow0) {
#pragma unroll
        for (int j = 0; j < 4; j++) {
            const int i = tid + j * 512;
            const int plane = i >> 10, row = (i >> 4) & 63, c16 = i & 15;
            const bf16* src = plane ? Vlp : Vhp;
            const uint32_t off = (uint32_t)(row * 256 + c16 * 16);
            cp_async16(Vr + buf * 32768 + plane * 16384 + (off ^ (uint32_t)((row & 7) << 4)),
                       src + (size_t)(krow0 + row) * Dd + c16 * 8);
        }
    };

    // QK: A = Q, B = K[64 keys]; accS[2][2][4]
    auto do_mma_qk = [&](float acc[2][2][4], uint32_t kbuf) {
#pragma unroll
        for (int c = 0; c < 2; c++) {
            const uint32_t aHb = Qb + c * 16384, aLb = Qb + 32768 + c * 16384;
            const uint32_t bHb = kbuf + c * 8192, bLb = kbuf + 16384 + c * 8192;
#pragma unroll
            for (int kk = 0; kk < 4; kk++) {
                uint32_t aH[2][4], aL[2][4];
#pragma unroll
                for (int t = 0; t < 2; t++) {
                    const int mrow = wm * 32 + t * 16 + (l & 7) + ((l >> 3) & 1) * 8;
                    const int kb = kk * 32 + ((l >> 4) & 1) * 16;
                    const uint32_t ao = (uint32_t)(mrow * 128) + (uint32_t)(kb ^ ((mrow & 7) << 4));
                    ldsm_x4(aH[t][0], aH[t][1], aH[t][2], aH[t][3], aHb + ao);
                    ldsm_x4(aL[t][0], aL[t][1], aL[t][2], aL[t][3], aLb + ao);
                }
                uint32_t bH[2][2], bL[2][2];
                {
                    const int nrow = wn * 16 + (l & 7) + ((l >> 4) & 1) * 8;
                    const int kb = kk * 32 + ((l >> 3) & 1) * 16;
                    const uint32_t bo = (uint32_t)(nrow * 128) + (uint32_t)(kb ^ ((nrow & 7) << 4));
                    ldsm_x4(bH[0][0], bH[0][1], bH[1][0], bH[1][1], bHb + bo);
                    ldsm_x4(bL[0][0], bL[0][1], bL[1][0], bL[1][1], bLb + bo);
                }
#pragma unroll
                for (int t = 0; t < 2; t++)
#pragma unroll
                    for (int nb = 0; nb < 2; nb++) {
                        mma_bf16(acc[t][nb], aH[t], bH[nb]);
                        mma_bf16(acc[t][nb], aH[t], bL[nb]);
                        mma_bf16(acc[t][nb], aL[t], bH[nb]);
                    }
            }
        }
    };

    // PV: A = P (64 keys contraction), B = V via trans; accO[2][4][4]
    auto do_mma_pv = [&](float acc[2][4][4], uint32_t vbuf) {
#pragma unroll
        for (int kk = 0; kk < 4; kk++) {
            uint32_t aH[2][4], aL[2][4];
#pragma unroll
            for (int t = 0; t < 2; t++) {
                const int mrow = wm * 32 + t * 16 + (l & 7) + ((l >> 3) & 1) * 8;
                const int kb = kk * 32 + ((l >> 4) & 1) * 16;
                const uint32_t ao = (uint32_t)(mrow * 128) + (uint32_t)(kb ^ ((mrow & 7) << 4));
                ldsm_x4(aH[t][0], aH[t][1], aH[t][2], aH[t][3], Pb + ao);
                ldsm_x4(aL[t][0], aL[t][1], aL[t][2], aL[t][3], Pb + 16384 + ao);
            }
            uint32_t bH[4][2], bL[4][2];
#pragma unroll
            for (int bt = 0; bt < 2; bt++) {
                const int key = kk * 16 + (l & 7) + ((l >> 3) & 1) * 8;
                const int colb = wn * 64 + bt * 32 + ((l >> 4) & 1) * 16;
                const uint32_t bo = (uint32_t)(key * 256) + (uint32_t)(colb ^ ((key & 7) << 4));
                ldsm_x4_t(bH[2 * bt][0], bH[2 * bt][1], bH[2 * bt + 1][0], bH[2 * bt + 1][1],
                          vbuf + bo);
                ldsm_x4_t(bL[2 * bt][0], bL[2 * bt][1], bL[2 * bt + 1][0], bL[2 * bt + 1][1],
                          vbuf + 16384 + bo);
            }
#pragma unroll
            for (int t = 0; t < 2; t++)
#pragma unroll
                for (int nb = 0; nb < 4; nb++) {
                    mma_bf16(acc[t][nb], aH[t], bH[nb]);
                    mma_bf16(acc[t][nb], aH[t], bL[nb]);
                    mma_bf16(acc[t][nb], aL[t], bH[nb]);
                }
        }
    };

    float accO[2][4][4];
#pragma unroll
    for (int t = 0; t < 2; t++)
#pragma unroll
        for (int nb = 0; nb < 4; nb++)
#pragma unroll
            for (int i = 0; i < 4; i++) accO[t][nb][i] = 0.f;
    float rs[4] = {0.f, 0.f, 0.f, 0.f};

    // prologue: Q + K0 + V0 in one group
    load_Q();
    load_K(0, key0);
    load_V(0, key0);
    CP_COMMIT();

    for (int it = 0; it < NIT; it++) {
        CP_WAIT(0);               // own copies of group it-1 (and prologue) done
        __syncthreads();          // all threads' copies visible; all done PV_{it-1}

        if (it + 1 < NIT) {       // prefetch next K/V (group it)
            load_K((it + 1) & 1, key0 + (it + 1) * KEYB);
            load_V((it + 1) & 1, key0 + (it + 1) * KEYB);
        }
        CP_COMMIT();              // empty group on last iter keeps cadence

        float accS[2][2][4];
#pragma unroll
        for (int t = 0; t < 2; t++)
#pragma unroll
            for (int nb = 0; nb < 2; nb++)
#pragma unroll
                for (int i = 0; i < 4; i++) accS[t][nb][i] = 0.f;

        do_mma_qk(accS, Kr + (it & 1) * 32768);

        // exp + split + STS P — register dependency only; warps drift so this
        // overlaps other warps' QK MMA issue (tensor pipe stays fed)
#pragma unroll
        for (int t = 0; t < 2; t++)
#pragma unroll
            for (int rh = 0; rh < 2; rh++) {
                const int row = wm * 32 + t * 16 + (l >> 2) + rh * 8;
#pragma unroll
                for (int nb = 0; nb < 2; nb++) {
                    const int col = wn * 16 + nb * 8 + (l & 3) * 2;
                    const float e0 = __expf(accS[t][nb][rh * 2 + 0]);
                    const float e1 = __expf(accS[t][nb][rh * 2 + 1]);
                    rs[t * 2 + rh] += e0 + e1;
                    uint32_t ph, pl;
                    split_pair(e0, e1, ph, pl);
                    const uint32_t off = (uint32_t)(row * 128 + col * 2);
                    const uint32_t sw = off ^ (uint32_t)((row & 7) << 4);
                    *(uint32_t*)(smem + (Pb - sb) + sw) = ph;
                    *(uint32_t*)(smem + (Pb - sb) + 16384 + sw) = pl;
                }
            }
        __syncthreads();          // P complete from all warps

        do_mma_pv(accO, Vr + (it & 1) * 32768);
    }

    // reduce row sums across quads + 4 n-warps
#pragma unroll
    for (int s = 0; s < 4; s++) {
        rs[s] += __shfl_xor_sync(0xffffffffu, rs[s], 1);
        rs[s] += __shfl_xor_sync(0xffffffffu, rs[s], 2);
    }
    __syncthreads();              // all PV done; rbuf free
    if ((l & 3) == 0) {
#pragma unroll
        for (int s = 0; s < 4; s++) {
            const int row = wm * 32 + (s >> 1) * 16 + (l >> 2) + (s & 1) * 8;
            rbuf[wn * 128 + row] = rs[s];
        }
    }
    __syncthreads();

    if (tid < 128) {
        g_rs[((size_t)sp * Hh + z) * Mq + bm + tid] =
            rbuf[tid] + rbuf[128 + tid] + rbuf[256 + tid] + rbuf[384 + tid];
    }

    float* obase = g_Opart + (((size_t)sp * Hh + z) * Mq + bm) * Dd;
#pragma unroll
    for (int t = 0; t < 2; t++)
#pragma unroll
        for (int rh = 0; rh < 2; rh++) {
            const int row = wm * 32 + t * 16 + (l >> 2) + rh * 8;
#pragma unroll
            for (int nb = 0; nb < 4; nb++) {
                const int col = wn * 32 + nb * 8 + (l & 3) * 2;
                float2 v;
                v.x = accO[t][nb][rh * 2 + 0];
                v.y = accO[t][nb][rh * 2 + 1];
                *(float2*)(obase + (size_t)row * Dd + col) = v;
            }
        }
}

// ---------------- combine partials -> out ----------------
__global__ __launch_bounds__(256) void combine_kernel(float* __restrict__ outp)
{
    const size_t idx = (size_t)blockIdx.x * blockDim.x + threadIdx.x;
    const size_t e = idx * 4;
    const int m = (int)(e >> 12);
    const int c = (int)(e & (Nn - 1));
    const int h = c >> 7;
    const int d = c & 127;

    const size_t rbase = (size_t)h * Mq + m;
    const float tot = g_rs[rbase] + g_rs[(size_t)Hh * Mq + rbase]
                    + g_rs[2 * (size_t)Hh * Mq + rbase] + g_rs[3 * (size_t)Hh * Mq + rbase];
    const float inv = 1.0f / tot;

    const size_t pbase = ((size_t)h * Mq + m) * Dd + d;
    const size_t pstep = (size_t)Hh * Mq * Dd;
    float4 a = *(const float4*)(g_Opart + pbase);
    float4 b = *(const float4*)(g_Opart + pbase + pstep);
    float4 cc = *(const float4*)(g_Opart + pbase + 2 * pstep);
    float4 dd = *(const float4*)(g_Opart + pbase + 3 * pstep);
    float4 o;
    o.x = (a.x + b.x + cc.x + dd.x) * inv;
    o.y = (a.y + b.y + cc.y + dd.y) * inv;
    o.z = (a.z + b.z + cc.z + dd.z) * inv;
    o.w = (a.w + b.w + cc.w + dd.w) * inv;
    *(float4*)(outp + e) = o;
}

// ---------------- prep ----------------
__global__ __launch_bounds__(256) void convert_inputs(
    const float* __restrict__ X, const float* __restrict__ cK, const float* __restrict__ cV)
{
    const size_t stride = (size_t)gridDim.x * blockDim.x;
    const size_t tid0 = (size_t)blockIdx.x * blockDim.x + threadIdx.x;

    for (size_t i = tid0; i < (size_t)Mq * Nn; i += stride) {
        bf16 h, lo;
        split_bf16(X[i], h, lo);
        g_Xh[i] = h; g_Xl[i] = lo;
    }
    const size_t nkv = (size_t)Hh * Pp * Dd;
    for (size_t i = tid0; i < nkv; i += stride) {
        const size_t h = i / ((size_t)Pp * Dd);
        const size_t r = i % ((size_t)Pp * Dd);
        const size_t o = h * (size_t)NKEYS * Dd + r;
        bf16 hh, lo;
        split_bf16(cK[i], hh, lo);
        g_Kh[o] = hh; g_Kl[o] = lo;
        split_bf16(cV[i], hh, lo);
        g_Vh[o] = hh; g_Vl[o] = lo;
    }
}

__global__ __launch_bounds__(256) void convert_W(
    const float* __restrict__ Wq, const float* __restrict__ Wk, const float* __restrict__ Wv)
{
    const int z = blockIdx.y;
    const float* W = (z == 0) ? Wq : (z == 1) ? Wk : Wv;
    bf16* oh = g_Wh + (size_t)z * Nn * Nn;
    bf16* ol = g_Wl + (size_t)z * Nn * Nn;
    const size_t n = (size_t)Nn * Nn;
    for (size_t i = (size_t)blockIdx.x * blockDim.x + threadIdx.x; i < n;
         i += (size_t)gridDim.x * blockDim.x) {
        bf16 h, lo;
        split_bf16(W[i], h, lo);
        oh[i] = h; ol[i] = lo;
    }
}

// ---------------- host launcher ----------------
extern "C" void kernel_launch(void* const* d_in, const int* in_sizes, int n_in,
                              void* d_out, int out_size)
{
    const float* X  = (const float*)d_in[0];
    const float* Wq = (const float*)d_in[1];
    const float* Wk = (const float*)d_in[2];
    const float* Wv = (const float*)d_in[3];
    const float* cK = (const float*)d_in[4];
    const float* cV = (const float*)d_in[5];
    float* out = (float*)d_out;

    bf16 *xh, *xl, *wh, *wl;
    cudaGetSymbolAddress((void**)&xh, g_Xh);
    cudaGetSymbolAddress((void**)&xl, g_Xl);
    cudaGetSymbolAddress((void**)&wh, g_Wh);
    cudaGetSymbolAddress((void**)&wl, g_Wl);

    cudaFuncSetAttribute(proj_kernel, cudaFuncAttributeMaxDynamicSharedMemorySize, SMEM_PROJ);
    cudaFuncSetAttribute(attn_kernel, cudaFuncAttributeMaxDynamicSharedMemorySize, SMEM_ATT);

    convert_inputs<<<4096, 256>>>(X, cK, cV);
    convert_W<<<dim3(4096, 3), 256>>>(Wq, Wk, Wv);

    proj_kernel<<<dim3(Nn / 128, Mq / 256, 3), 256, SMEM_PROJ>>>(xh, xl, wh, wl);

    attn_kernel<<<dim3(Mq / 128, Hh, NSPLIT), 512, SMEM_ATT>>>();

    combine_kernel<<<(Mq * Nn / 4) / 256, 256>>>(out);
}